// round 10
// baseline (speedup 1.0000x reference)
#include <cuda_runtime.h>
#include <math.h>
#include <stdint.h>

// Problem constants
#define E   1024
#define A   64
#define H   16
#define FFD 4096
#define B   2
#define S   2048
#define M   (B*S)
#define NQKV (3*E)

// ---------------- scratch (device globals) -----------------------------------
__device__ float g_x[M*E];           // full-precision x (residual)
__device__ float g_x32[M*E];         // tf32-rounded x (GEMM A)
__device__ float g_wqkvT[NQKV*E];    // tf32 fused W^T [3E][E]  (n-major)
__device__ float g_wpT[E*E];         // tf32 Wproj^T [E][E]
__device__ float g_w1T[FFD*E];       // tf32 W1^T [FFD][E]
__device__ float g_w2T[E*FFD];       // tf32 W2^T [E][FFD]
__device__ float g_qkv[M*E];         // proj output scratch
__device__ float g_q[H*B*S*A];       // tf32 Q [hb][s][a]
__device__ float g_kt[H*B*A*S];      // tf32 K^T [hb][a][s]
__device__ float g_attn[M*E];        // tf32-rounded attention out
__device__ float g_mha[M*E];         // full mha (residuals)
__device__ float g_mha32[M*E];       // tf32 mha (FFN1 A)
__device__ float g_hidden[M*FFD];    // tf32-rounded hidden
__device__ float g_ff[M*E];
__device__ float g_ffout[M*E];

// ---------------- helpers -------------------------------------------------------
__device__ __forceinline__ float ftf32(float x) {
    float y;
    asm("cvt.rna.tf32.f32 %0, %1;" : "=f"(y) : "f"(x));
    return y;
}
__device__ __forceinline__ float4 ftf32_4(float4 v) {
    v.x = ftf32(v.x); v.y = ftf32(v.y); v.z = ftf32(v.z); v.w = ftf32(v.w);
    return v;
}
__device__ __forceinline__ uint32_t smem_u32(const void* p) {
    uint32_t r;
    asm("{ .reg .u64 t; cvta.to.shared.u64 t, %1; cvt.u32.u64 %0, t; }"
        : "=r"(r) : "l"(p));
    return r;
}
#define CP16(dst, src) \
    asm volatile("cp.async.cg.shared.global [%0], [%1], 16;" \
                 :: "r"(dst), "l"(src) : "memory")
#define CP_COMMIT() asm volatile("cp.async.commit_group;" ::: "memory")
#define CP_WAIT(n)  asm volatile("cp.async.wait_group %0;" :: "n"(n) : "memory")
#define MMA_TF32(d, a0,a1,a2,a3, b0,b1)                                       \
    asm volatile(                                                             \
        "mma.sync.aligned.m16n8k8.row.col.f32.tf32.tf32.f32 "                 \
        "{%0,%1,%2,%3}, {%4,%5,%6,%7}, {%8,%9}, {%0,%1,%2,%3};"               \
        : "+f"((d)[0]), "+f"((d)[1]), "+f"((d)[2]), "+f"((d)[3])              \
        : "r"(a0), "r"(a1), "r"(a2), "r"(a3), "r"(b0), "r"(b1))
#define LDSM4(r, addr)                                                        \
    asm volatile("ldmatrix.sync.aligned.m8n8.x4.shared.b16 {%0,%1,%2,%3}, [%4];" \
        : "=r"((r)[0]), "=r"((r)[1]), "=r"((r)[2]), "=r"((r)[3]) : "r"(addr))
#define LDSM2(r, addr)                                                        \
    asm volatile("ldmatrix.sync.aligned.m8n8.x2.shared.b16 {%0,%1}, [%2];"    \
        : "=r"((r)[0]), "=r"((r)[1]) : "r"(addr))
#define FAU(x) __float_as_uint(x)

// ---------------- x = emb + pos (full + tf32 copy) ------------------------------
__global__ void k_add(const float4* __restrict__ a, const float4* __restrict__ b,
                      float4* __restrict__ o, float4* __restrict__ o32) {
    int i = blockIdx.x * blockDim.x + threadIdx.x;
    float4 x = a[i], y = b[i];
    x.x += y.x; x.y += y.y; x.z += y.z; x.w += y.w;
    o[i] = x;
    o32[i] = ftf32_4(x);
}

// ---------------- tiled transpose + tf32 round: [R][C] -> [C][R], batched -------
__global__ void k_tr(const float* __restrict__ in, float* __restrict__ out,
                     int R, int C, long ibs, long obs) {
    __shared__ float t[32][33];
    const float* ip = in + (size_t)blockIdx.z * ibs;
    float* op = out + (size_t)blockIdx.z * obs;
    int c0 = blockIdx.x * 32, r0 = blockIdx.y * 32;
    int tx = threadIdx.x, ty = threadIdx.y;
#pragma unroll
    for (int j = 0; j < 4; j++)
        t[ty + j*8][tx] = ip[(size_t)(r0 + ty + j*8) * C + c0 + tx];
    __syncthreads();
#pragma unroll
    for (int j = 0; j < 4; j++)
        op[(size_t)(c0 + ty + j*8) * R + r0 + tx] = ftf32(t[tx][ty + j*8]);
}

// ---------------- tf32 mma.sync GEMM, cp.async 3-stage, ldmatrix feeding ---------
// A [Md][Kd] tf32 row-major; BT [Nd][Kd] tf32 n-major. Tile 128x128x16.
// smem per stage: A [128][20] + BT [128][20] floats (pitch 80B, LDSM-conflict-free)
#define STG_F 5120
#define GEMM_SMEM (3 * STG_F * 4)

__global__ __launch_bounds__(256, 2)
void k_gemm_tc(const float* __restrict__ Ag, const float* __restrict__ BTg,
               float* __restrict__ Cg, int Nd, int Kd,
               const float* __restrict__ bias, const float* __restrict__ resid,
               int do_relu, int out_tf32, int qkv_mode,
               float* __restrict__ qd, float* __restrict__ kd,
               float* __restrict__ vd, float* __restrict__ ktd) {
    extern __shared__ float smf[];
    uint32_t sb = smem_u32(smf);

    int tid = threadIdx.x;
    int lane = tid & 31, wid = tid >> 5;
    int wm = wid & 1, wn = wid >> 1;
    int gid = lane >> 2, qid = lane & 3;

    const float* Ab = Ag + (size_t)blockIdx.y * 128 * Kd;
    const float* Bb = BTg + (size_t)blockIdx.x * 128 * Kd;

    // cp.async chunk mapping (identical for A and BT: 128 rows x 16 floats)
    int c1 = tid, c2 = tid + 256;
    int r1c = c1 >> 2, o1c = (c1 & 3) * 16, k1c = (c1 & 3) * 4;
    int r2c = c2 >> 2, o2c = (c2 & 3) * 16, k2c = (c2 & 3) * 4;

    // ldmatrix per-thread address offsets (bytes, within a stage)
    int a_row = (lane & 7) + ((lane >> 3) & 1) * 8;   // sub-tile row
    int a_col = (lane >> 4) * 16;                     // +16B for k 4..7
    int b_row = lane & 7;
    int b_col = ((lane >> 3) & 1) * 16;
    uint32_t aoff[4], boff[4];
#pragma unroll
    for (int mi = 0; mi < 4; mi++)
        aoff[mi] = (wm * 64 + mi * 16 + a_row) * 80 + a_col;
#pragma unroll
    for (int ni = 0; ni < 4; ni++)
        boff[ni] = 2560 * 4 + (wn * 32 + ni * 8 + b_row) * 80 + b_col;

    float acc[4][4][4];
#pragma unroll
    for (int i = 0; i < 4; i++)
#pragma unroll
        for (int j = 0; j < 4; j++)
#pragma unroll
            for (int r = 0; r < 4; r++) acc[i][j][r] = 0.f;

    int nk = Kd >> 4;

#define LOAD_STAGE(s, k0)                                                     \
    do {                                                                      \
        uint32_t A0 = sb + (s) * (STG_F * 4);                                 \
        uint32_t B0 = A0 + 2560 * 4;                                          \
        CP16(A0 + r1c * 80 + o1c, Ab + (size_t)r1c * Kd + (k0) + k1c);        \
        CP16(A0 + r2c * 80 + o2c, Ab + (size_t)r2c * Kd + (k0) + k2c);        \
        CP16(B0 + r1c * 80 + o1c, Bb + (size_t)r1c * Kd + (k0) + k1c);        \
        CP16(B0 + r2c * 80 + o2c, Bb + (size_t)r2c * Kd + (k0) + k2c);        \
        CP_COMMIT();                                                          \
    } while (0)

    LOAD_STAGE(0, 0);
    LOAD_STAGE(1, 16);

    int buf = 0;
    for (int kc = 0; kc < nk; kc++) {
        if (kc + 2 < nk) { CP_WAIT(1); } else { CP_WAIT(0); }
        __syncthreads();
        if (kc + 2 < nk) {
            int s = (kc + 2) % 3;
            LOAD_STAGE(s, (kc + 2) * 16);
        }
        uint32_t st = sb + buf * (STG_F * 4);
#pragma unroll
        for (int ks4 = 0; ks4 <= 32; ks4 += 32) {
            unsigned af[4][4], bf[4][2];
#pragma unroll
            for (int mi = 0; mi < 4; mi++) LDSM4(af[mi], st + aoff[mi] + ks4);
#pragma unroll
            for (int ni = 0; ni < 4; ni++) LDSM2(bf[ni], st + boff[ni] + ks4);
#pragma unroll
            for (int mi = 0; mi < 4; mi++)
#pragma unroll
                for (int ni = 0; ni < 4; ni++)
                    MMA_TF32(acc[mi][ni], af[mi][0], af[mi][1], af[mi][2],
                             af[mi][3], bf[ni][0], bf[ni][1]);
        }
        buf = (buf + 1) % 3;
    }
#undef LOAD_STAGE

    // epilogue
    int bn = blockIdx.x * 128;
#pragma unroll
    for (int mi = 0; mi < 4; mi++) {
        int r0 = blockIdx.y * 128 + wm * 64 + mi * 16 + gid;
        int r1 = r0 + 8;
#pragma unroll
        for (int ni = 0; ni < 4; ni++) {
            int col = bn + wn * 32 + ni * 8 + 2 * qid;
            float2 v0 = make_float2(acc[mi][ni][0], acc[mi][ni][1]);
            float2 v1 = make_float2(acc[mi][ni][2], acc[mi][ni][3]);
            if (qkv_mode) {
                int which = col >> 10;
                int cc = col & 1023;
                int hh = cc >> 6, aa = cc & 63;
                int bb = r0 >> 11;
                int s0r = r0 & 2047, s1r = r1 & 2047;
                int hb_ = hh * B + bb;
                size_t d0 = (((size_t)hb_ * S + s0r) * A + aa);
                size_t d1 = (((size_t)hb_ * S + s1r) * A + aa);
                if (which == 0) {
                    v0.x = ftf32(v0.x); v0.y = ftf32(v0.y);
                    v1.x = ftf32(v1.x); v1.y = ftf32(v1.y);
                    *(float2*)(qd + d0) = v0;
                    *(float2*)(qd + d1) = v1;
                } else if (which == 1) {
                    *(float2*)(kd + d0) = v0;
                    *(float2*)(kd + d1) = v1;
                    size_t kt0 = ((size_t)hb_ * A + aa) * S;
                    ktd[kt0 + s0r]     = ftf32(v0.x);
                    ktd[kt0 + S + s0r] = ftf32(v0.y);
                    ktd[kt0 + s1r]     = ftf32(v1.x);
                    ktd[kt0 + S + s1r] = ftf32(v1.y);
                } else {
                    *(float2*)(vd + d0) = v0;
                    *(float2*)(vd + d1) = v1;
                }
            } else {
                if (bias) {
                    float2 bv = *(const float2*)(bias + col);
                    v0.x += bv.x; v0.y += bv.y; v1.x += bv.x; v1.y += bv.y;
                }
                if (resid) {
                    float2 q0 = *(const float2*)(resid + (size_t)r0 * Nd + col);
                    float2 q1 = *(const float2*)(resid + (size_t)r1 * Nd + col);
                    v0.x += q0.x; v0.y += q0.y; v1.x += q1.x; v1.y += q1.y;
                }
                if (do_relu) {
                    v0.x = fmaxf(v0.x, 0.f); v0.y = fmaxf(v0.y, 0.f);
                    v1.x = fmaxf(v1.x, 0.f); v1.y = fmaxf(v1.y, 0.f);
                }
                if (out_tf32) {
                    v0.x = ftf32(v0.x); v0.y = ftf32(v0.y);
                    v1.x = ftf32(v1.x); v1.y = ftf32(v1.y);
                }
                *(float2*)(Cg + (size_t)r0 * Nd + col) = v0;
                *(float2*)(Cg + (size_t)r1 * Nd + col) = v1;
            }
        }
    }
}

// ---------------- tensor-core flash attention (R9) -------------------------------
#define QSP 68
#define KTP 72
#define ATT_SMEM ((2 * 128 * QSP + 2 * 64 * KTP) * 4)

__global__ __launch_bounds__(256, 2)
void k_attn(const float* __restrict__ Qg, const float* __restrict__ Ktg,
            const float* __restrict__ Vg, float* __restrict__ attn_out) {
    extern __shared__ float sm[];
    float* Qs = sm;
    float* Ps = Qs + 128 * QSP;
    float* Kt = Ps + 128 * QSP;
    float* Vs = Kt + 64 * KTP;

    int tid = threadIdx.x, lane = tid & 31, wid = tid >> 5;
    int gid = lane >> 2, qid = lane & 3;
    int hb = blockIdx.y, qt = blockIdx.x;
    int h = hb / B, b = hb - h * B;
    int q0 = qt * 128;

    const float4* Q4 = (const float4*)(Qg + ((size_t)hb * S + q0) * A);
#pragma unroll
    for (int j = 0; j < 8; j++) {
        int i = tid + j * 256;
        int r = i >> 4, c = i & 15;
        *(float4*)&Qs[r * QSP + c * 4] = Q4[i];
    }

    int wr = wid * 16;
    int r0g = q0 + wr + gid, r1g = r0g + 8;
    float m0 = -INFINITY, m1 = -INFINITY, l0 = 0.f, l1 = 0.f;
    float o[8][4];
#pragma unroll
    for (int nt = 0; nt < 8; nt++)
#pragma unroll
        for (int c = 0; c < 4; c++) o[nt][c] = 0.f;

    const float scale = 0.03125f;
    int ntl = 2 * qt + 2;
    const float4* Kt4 = (const float4*)(Ktg + (size_t)hb * A * S);
    const float4* V4g = (const float4*)(Vg + (size_t)hb * S * A);

    for (int t = 0; t < ntl; t++) {
        int k0 = t * 64;
        __syncthreads();
#pragma unroll
        for (int j = 0; j < 4; j++) {
            int i = tid + j * 256;
            int d = i >> 4, q4 = i & 15;
            float4 kv = Kt4[d * (S / 4) + (k0 >> 2) + q4];
            *(float4*)&Kt[d * KTP + q4 * 4] = kv;
            float4 vv = V4g[(size_t)(k0 + d) * 16 + q4];
            *(float4*)&Vs[d * KTP + q4 * 4] = ftf32_4(vv);
        }
        __syncthreads();

        if (k0 <= q0 + wr + 15) {
            float sa[8][4];
#pragma unroll
            for (int nt = 0; nt < 8; nt++)
#pragma unroll
                for (int c = 0; c < 4; c++) sa[nt][c] = 0.f;
#pragma unroll
            for (int ks = 0; ks < 64; ks += 8) {
                unsigned a0 = FAU(Qs[(wr + gid) * QSP + ks + qid]);
                unsigned a1 = FAU(Qs[(wr + gid + 8) * QSP + ks + qid]);
                unsigned a2 = FAU(Qs[(wr + gid) * QSP + ks + qid + 4]);
                unsigned a3 = FAU(Qs[(wr + gid + 8) * QSP + ks + qid + 4]);
#pragma unroll
                for (int nt = 0; nt < 8; nt++) {
                    unsigned b0 = FAU(Kt[(ks + qid) * KTP + nt * 8 + gid]);
                    unsigned b1 = FAU(Kt[(ks + qid + 4) * KTP + nt * 8 + gid]);
                    MMA_TF32(sa[nt], a0, a1, a2, a3, b0, b1);
                }
            }
            float mx0 = -INFINITY, mx1 = -INFINITY;
#pragma unroll
            for (int nt = 0; nt < 8; nt++) {
                int colb = k0 + nt * 8 + 2 * qid;
                sa[nt][0] = (colb     <= r0g) ? sa[nt][0] * scale : -INFINITY;
                sa[nt][1] = (colb + 1 <= r0g) ? sa[nt][1] * scale : -INFINITY;
                sa[nt][2] = (colb     <= r1g) ? sa[nt][2] * scale : -INFINITY;
                sa[nt][3] = (colb + 1 <= r1g) ? sa[nt][3] * scale : -INFINITY;
                mx0 = fmaxf(mx0, fmaxf(sa[nt][0], sa[nt][1]));
                mx1 = fmaxf(mx1, fmaxf(sa[nt][2], sa[nt][3]));
            }
            mx0 = fmaxf(mx0, __shfl_xor_sync(0xffffffff, mx0, 1));
            mx0 = fmaxf(mx0, __shfl_xor_sync(0xffffffff, mx0, 2));
            mx1 = fmaxf(mx1, __shfl_xor_sync(0xffffffff, mx1, 1));
            mx1 = fmaxf(mx1, __shfl_xor_sync(0xffffffff, mx1, 2));
            float mn0 = fmaxf(m0, mx0), mn1 = fmaxf(m1, mx1);
            float al0 = __expf(m0 - mn0), al1 = __expf(m1 - mn1);
            float sum0 = 0.f, sum1 = 0.f;
#pragma unroll
            for (int nt = 0; nt < 8; nt++) {
                sa[nt][0] = __expf(sa[nt][0] - mn0); sum0 += sa[nt][0];
                sa[nt][1] = __expf(sa[nt][1] - mn0); sum0 += sa[nt][1];
                sa[nt][2] = __expf(sa[nt][2] - mn1); sum1 += sa[nt][2];
                sa[nt][3] = __expf(sa[nt][3] - mn1); sum1 += sa[nt][3];
            }
            sum0 += __shfl_xor_sync(0xffffffff, sum0, 1);
            sum0 += __shfl_xor_sync(0xffffffff, sum0, 2);
            sum1 += __shfl_xor_sync(0xffffffff, sum1, 1);
            sum1 += __shfl_xor_sync(0xffffffff, sum1, 2);
            l0 = l0 * al0 + sum0;  m0 = mn0;
            l1 = l1 * al1 + sum1;  m1 = mn1;
#pragma unroll
            for (int nt = 0; nt < 8; nt++) {
                o[nt][0] *= al0; o[nt][1] *= al0;
                o[nt][2] *= al1; o[nt][3] *= al1;
            }
#pragma unroll
            for (int nt = 0; nt < 8; nt++) {
                *(float2*)&Ps[(wr + gid) * QSP + nt * 8 + 2 * qid] =
                    make_float2(ftf32(sa[nt][0]), ftf32(sa[nt][1]));
                *(float2*)&Ps[(wr + gid + 8) * QSP + nt * 8 + 2 * qid] =
                    make_float2(ftf32(sa[nt][2]), ftf32(sa[nt][3]));
            }
            __syncwarp();
#pragma unroll
            for (int ks = 0; ks < 64; ks += 8) {
                unsigned a0 = FAU(Ps[(wr + gid) * QSP + ks + qid]);
                unsigned a1 = FAU(Ps[(wr + gid + 8) * QSP + ks + qid]);
                unsigned a2 = FAU(Ps[(wr + gid) * QSP + ks + qid + 4]);
                unsigned a3 = FAU(Ps[(wr + gid + 8) * QSP + ks + qid + 4]);
#pragma unroll
                for (int nt = 0; nt < 8; nt++) {
                    unsigned b0 = FAU(Vs[(ks + qid) * KTP + nt * 8 + gid]);
                    unsigned b1 = FAU(Vs[(ks + qid + 4) * KTP + nt * 8 + gid]);
                    MMA_TF32(o[nt], a0, a1, a2, a3, b0, b1);
                }
            }
        }
    }

    float il0 = 1.f / l0, il1 = 1.f / l1;
    int row0 = b * S + q0 + wr + gid;
    int row1 = row0 + 8;
#pragma unroll
    for (int nt = 0; nt < 8; nt++) {
        int col = h * A + nt * 8 + 2 * qid;
        *(float2*)(attn_out + (size_t)row0 * E + col) =
            make_float2(ftf32(o[nt][0] * il0), ftf32(o[nt][1] * il0));
        *(float2*)(attn_out + (size_t)row1 * E + col) =
            make_float2(ftf32(o[nt][2] * il1), ftf32(o[nt][3] * il1));
    }
}

// ---------------- LayerNorm (optional tf32 second output) -----------------------
__global__ __launch_bounds__(256)
void k_ln(const float* __restrict__ a, const float* __restrict__ b,
          const float* __restrict__ gg, const float* __restrict__ bb,
          float* __restrict__ o, float* __restrict__ o32) {
    __shared__ float red[16];
    __shared__ float s_mu, s_rstd;
    int row = blockIdx.x;
    int t = threadIdx.x;
    float4 x = ((const float4*)(a + (size_t)row * E))[t];
    if (b) {
        float4 y = ((const float4*)(b + (size_t)row * E))[t];
        x.x += y.x; x.y += y.y; x.z += y.z; x.w += y.w;
    }
    float sum = x.x + x.y + x.z + x.w;
    float sq  = x.x*x.x + x.y*x.y + x.z*x.z + x.w*x.w;
#pragma unroll
    for (int off = 16; off; off >>= 1) {
        sum += __shfl_xor_sync(0xffffffff, sum, off);
        sq  += __shfl_xor_sync(0xffffffff, sq,  off);
    }
    if ((t & 31) == 0) { red[t >> 5] = sum; red[8 + (t >> 5)] = sq; }
    __syncthreads();
    if (t == 0) {
        float ts = 0.f, tq = 0.f;
#pragma unroll
        for (int i = 0; i < 8; i++) { ts += red[i]; tq += red[8 + i]; }
        float mu = ts * (1.f / E);
        float var = tq * (1.f / E) - mu * mu;
        s_mu = mu; s_rstd = rsqrtf(var + 1e-5f);
    }
    __syncthreads();
    float mu = s_mu, rstd = s_rstd;
    float4 g4 = ((const float4*)gg)[t];
    float4 b4 = ((const float4*)bb)[t];
    float4 rr;
    rr.x = (x.x - mu) * rstd * g4.x + b4.x;
    rr.y = (x.y - mu) * rstd * g4.y + b4.y;
    rr.z = (x.z - mu) * rstd * g4.z + b4.z;
    rr.w = (x.w - mu) * rstd * g4.w + b4.w;
    ((float4*)(o + (size_t)row * E))[t] = rr;
    if (o32) ((float4*)(o32 + (size_t)row * E))[t] = ftf32_4(rr);
}

// ---------------- launch ----------------------------------------------------------
extern "C" void kernel_launch(void* const* d_in, const int* in_sizes, int n_in,
                              void* d_out, int out_size) {
    const float* emb    = (const float*)d_in[0];
    const float* pos    = (const float*)d_in[1];
    const float* Wq     = (const float*)d_in[2];
    const float* Wk     = (const float*)d_in[3];
    const float* Wv     = (const float*)d_in[4];
    const float* Wproj  = (const float*)d_in[5];
    const float* W1     = (const float*)d_in[6];
    const float* b1     = (const float*)d_in[7];
    const float* W2     = (const float*)d_in[8];
    const float* b2     = (const float*)d_in[9];
    const float* gattn  = (const float*)d_in[10];
    const float* beattn = (const float*)d_in[11];
    const float* gffn   = (const float*)d_in[12];
    const float* beffn  = (const float*)d_in[13];
    const float* gout   = (const float*)d_in[14];
    const float* beout  = (const float*)d_in[15];

    float* out  = (float*)d_out;
    float* Kout = out + (size_t)M * E;
    float* Vout = out + (size_t)2 * M * E;

    float *px, *px32, *pw, *pwp, *pw1, *pw2, *pqkv, *pq, *pkt, *pattn;
    float *pmha, *pmha32, *phid, *pff, *pffout;
    cudaGetSymbolAddress((void**)&px,    g_x);
    cudaGetSymbolAddress((void**)&px32,  g_x32);
    cudaGetSymbolAddress((void**)&pw,    g_wqkvT);
    cudaGetSymbolAddress((void**)&pwp,   g_wpT);
    cudaGetSymbolAddress((void**)&pw1,   g_w1T);
    cudaGetSymbolAddress((void**)&pw2,   g_w2T);
    cudaGetSymbolAddress((void**)&pqkv,  g_qkv);
    cudaGetSymbolAddress((void**)&pq,    g_q);
    cudaGetSymbolAddress((void**)&pkt,   g_kt);
    cudaGetSymbolAddress((void**)&pattn, g_attn);
    cudaGetSymbolAddress((void**)&pmha,  g_mha);
    cudaGetSymbolAddress((void**)&pmha32,g_mha32);
    cudaGetSymbolAddress((void**)&phid,  g_hidden);
    cudaGetSymbolAddress((void**)&pff,   g_ff);
    cudaGetSymbolAddress((void**)&pffout,g_ffout);

    cudaFuncSetAttribute(k_attn, cudaFuncAttributeMaxDynamicSharedMemorySize,
                         ATT_SMEM);
    cudaFuncSetAttribute(k_gemm_tc, cudaFuncAttributeMaxDynamicSharedMemorySize,
                         GEMM_SMEM);

    dim3 trb(32, 8);
    // 1: x = emb + pos (+ tf32 copy)
    k_add<<<(M * E / 4) / 256, 256>>>((const float4*)emb, (const float4*)pos,
                                      (float4*)px, (float4*)px32);
    // 2-7: weight transposes to [N][K] with tf32 rounding
    k_tr<<<dim3(A/32, E/32, H), trb>>>(Wq, pw,                    E, A, (long)E*A, (long)A*E);
    k_tr<<<dim3(A/32, E/32, H), trb>>>(Wk, pw + (size_t)E*E,      E, A, (long)E*A, (long)A*E);
    k_tr<<<dim3(A/32, E/32, H), trb>>>(Wv, pw + (size_t)2*E*E,    E, A, (long)E*A, (long)A*E);
    k_tr<<<dim3(E/32, E/32, 1), trb>>>(Wproj, pwp, E, E, 0, 0);
    k_tr<<<dim3(FFD/32, E/32, 1), trb>>>(W1, pw1, E, FFD, 0, 0);
    k_tr<<<dim3(E/32, FFD/32, 1), trb>>>(W2, pw2, FFD, E, 0, 0);

    // QKV GEMM -> Q(tf32) + K/V d_out + K^T(tf32)
    k_gemm_tc<<<dim3(NQKV/128, M/128), 256, GEMM_SMEM>>>(
        px32, pw, nullptr, NQKV, E, nullptr, nullptr, 0, 0, 1, pq, Kout, Vout, pkt);
    // tensor-core flash attention
    k_attn<<<dim3(S/128, H*B), 256, ATT_SMEM>>>(pq, pkt, Vout, pattn);
    // proj + residual(x full)
    k_gemm_tc<<<dim3(E/128, M/128), 256, GEMM_SMEM>>>(
        pattn, pwp, pqkv, E, E, nullptr, px, 0, 0, 0, nullptr, nullptr, nullptr, nullptr);
    k_ln<<<M, 256>>>(pqkv, nullptr, gattn, beattn, pmha, pmha32);
    // FFN1 (+b1, tf32-rounded output)
    k_gemm_tc<<<dim3(FFD/128, M/128), 256, GEMM_SMEM>>>(
        pmha32, pw1, phid, FFD, E, b1, nullptr, 0, 1, 0, nullptr, nullptr, nullptr, nullptr);
    // FFN2 (+b2, relu)
    k_gemm_tc<<<dim3(E/128, M/128), 256, GEMM_SMEM>>>(
        phid, pw2, pff, E, FFD, b2, nullptr, 1, 0, 0, nullptr, nullptr, nullptr, nullptr);
    k_ln<<<M, 256>>>(pmha, pff, gffn, beffn, pffout, nullptr);
    k_ln<<<M, 256>>>(pmha, pffout, gout, beout, out, nullptr);
}

// round 13
// speedup vs baseline: 1.7611x; 1.7611x over previous
#include <cuda_runtime.h>
#include <cuda_fp16.h>
#include <math.h>
#include <stdint.h>

// Problem constants
#define E   1024
#define A   64
#define H   16
#define FFD 4096
#define B   2
#define S   2048
#define M   (B*S)
#define NQKV (3*E)

// ---------------- scratch (device globals) -----------------------------------
__device__ float  g_x[M*E];          // fp32 x (residual)
__device__ __half g_x16[M*E];        // fp16 x (GEMM A)
__device__ __half g_wqkvT[NQKV*E];   // fp16 fused W^T [3E][E]
__device__ __half g_wpT[E*E];        // fp16 Wproj^T
__device__ __half g_w1T[FFD*E];      // fp16 W1^T
__device__ __half g_w2T[E*FFD];      // fp16 W2^T
__device__ float  g_qkv[M*E];        // proj out (fp32, pre-LN)
__device__ __half g_q16[M*E];        // fp16 Q [hb][s][a]
__device__ __half g_kh[M*E];         // fp16 K [hb][s][a]
__device__ __half g_vt[M*E];         // fp16 V^T [hb][a][s]
__device__ __half g_attn16[M*E];     // fp16 attention out
__device__ float  g_mha[M*E];        // fp32 mha (residual)
__device__ __half g_mha16[M*E];      // fp16 mha (FFN1 A)
__device__ __half g_hid16[M*FFD];    // fp16 hidden (FFN2 A)
__device__ float  g_ff[M*E];
__device__ float  g_ffout[M*E];

// ---------------- helpers -------------------------------------------------------
__device__ __forceinline__ uint32_t smem_u32(const void* p) {
    uint32_t r;
    asm("{ .reg .u64 t; cvta.to.shared.u64 t, %1; cvt.u32.u64 %0, t; }"
        : "=r"(r) : "l"(p));
    return r;
}
__device__ __forceinline__ uint32_t h2pack(float x, float y) {
    __half2 h = __floats2half2_rn(x, y);
    return *(uint32_t*)&h;
}
#define CP16(dst, src) \
    asm volatile("cp.async.cg.shared.global [%0], [%1], 16;" \
                 :: "r"(dst), "l"(src) : "memory")
#define CP_COMMIT() asm volatile("cp.async.commit_group;" ::: "memory")
#define CP_WAIT(n)  asm volatile("cp.async.wait_group %0;" :: "n"(n) : "memory")
#define MMA_F16(d, a0,a1,a2,a3, b0,b1)                                        \
    asm volatile(                                                             \
        "mma.sync.aligned.m16n8k16.row.col.f32.f16.f16.f32 "                  \
        "{%0,%1,%2,%3}, {%4,%5,%6,%7}, {%8,%9}, {%0,%1,%2,%3};"               \
        : "+f"((d)[0]), "+f"((d)[1]), "+f"((d)[2]), "+f"((d)[3])              \
        : "r"(a0), "r"(a1), "r"(a2), "r"(a3), "r"(b0), "r"(b1))
#define LDU32(p) (*(const uint32_t*)(p))

// ---------------- x = emb + pos (fp32 + fp16 copy) -------------------------------
__global__ void k_add(const float4* __restrict__ a, const float4* __restrict__ b,
                      float4* __restrict__ o, uint2* __restrict__ o16) {
    int i = blockIdx.x * blockDim.x + threadIdx.x;
    float4 x = a[i], y = b[i];
    x.x += y.x; x.y += y.y; x.z += y.z; x.w += y.w;
    o[i] = x;
    uint2 h;
    h.x = h2pack(x.x, x.y);
    h.y = h2pack(x.z, x.w);
    o16[i] = h;
}

// ---------------- tiled transpose fp32 [R][C] -> fp16 [C][R], batched ------------
__global__ void k_tr(const float* __restrict__ in, __half* __restrict__ out,
                     int R, int C, long ibs, long obs) {
    __shared__ float t[32][33];
    const float* ip = in + (size_t)blockIdx.z * ibs;
    __half* op = out + (size_t)blockIdx.z * obs;
    int c0 = blockIdx.x * 32, r0 = blockIdx.y * 32;
    int tx = threadIdx.x, ty = threadIdx.y;
#pragma unroll
    for (int j = 0; j < 4; j++)
        t[ty + j*8][tx] = ip[(size_t)(r0 + ty + j*8) * C + c0 + tx];
    __syncthreads();
#pragma unroll
    for (int j = 0; j < 4; j++)
        op[(size_t)(c0 + ty + j*8) * R + r0 + tx] = __float2half_rn(t[tx][ty + j*8]);
}

// ---------------- fp16 mma GEMM, cp.async 3-stage --------------------------------
// A [Md][Kd] half row-major; BT [Nd][Kd] half n-major. Tile 128x128, k-chunk 32.
#define PBY 80
#define STG_B (256 * PBY)
#define GEMM_SMEM (3 * STG_B)

__global__ __launch_bounds__(256, 2)
void k_gemm_h(const __half* __restrict__ Ag, const __half* __restrict__ BTg,
              float* __restrict__ Cg, __half* __restrict__ Cg16,
              int Nd, int Kd,
              const float* __restrict__ bias, const float* __restrict__ resid,
              int do_relu, int qkv_mode,
              __half* __restrict__ qd, float* __restrict__ kd,
              float* __restrict__ vd, __half* __restrict__ khd,
              __half* __restrict__ vtd) {
    extern __shared__ char smh[];
    uint32_t sb = smem_u32(smh);

    int tid = threadIdx.x;
    int lane = tid & 31, wid = tid >> 5;
    int wm = wid & 1, wn = wid >> 1;
    int gid = lane >> 2, qid = lane & 3;

    const __half* Ab = Ag + (size_t)blockIdx.y * 128 * Kd;
    const __half* Bb = BTg + (size_t)blockIdx.x * 128 * Kd;

    int cr = tid >> 2;
    int co = tid & 3;

    float acc[4][4][4];
#pragma unroll
    for (int i = 0; i < 4; i++)
#pragma unroll
        for (int j = 0; j < 4; j++)
#pragma unroll
            for (int r = 0; r < 4; r++) acc[i][j][r] = 0.f;

    int nk = Kd >> 5;

#define LOAD_STAGE(s, k0)                                                     \
    do {                                                                      \
        uint32_t A0 = sb + (s) * STG_B;                                       \
        uint32_t B0 = A0 + 128 * PBY;                                         \
        CP16(A0 + cr * PBY + co * 16,        Ab + (size_t)cr * Kd + (k0) + co * 8); \
        CP16(A0 + (cr + 64) * PBY + co * 16, Ab + (size_t)(cr + 64) * Kd + (k0) + co * 8); \
        CP16(B0 + cr * PBY + co * 16,        Bb + (size_t)cr * Kd + (k0) + co * 8); \
        CP16(B0 + (cr + 64) * PBY + co * 16, Bb + (size_t)(cr + 64) * Kd + (k0) + co * 8); \
        CP_COMMIT();                                                          \
    } while (0)

    LOAD_STAGE(0, 0);
    LOAD_STAGE(1, 32);

    int buf = 0;
    for (int kc = 0; kc < nk; kc++) {
        if (kc + 2 < nk) { CP_WAIT(1); } else { CP_WAIT(0); }
        __syncthreads();
        if (kc + 2 < nk) {
            int s = (kc + 2) % 3;
            LOAD_STAGE(s, (kc + 2) * 32);
        }
        const char* st = smh + buf * STG_B;
        const char* stB = st + 128 * PBY;
#pragma unroll
        for (int j = 0; j < 2; j++) {
            int jb = j * 32;
            unsigned af[4][4], bf[4][2];
#pragma unroll
            for (int mi = 0; mi < 4; mi++) {
                int row = wm * 64 + mi * 16 + gid;
                const char* p0 = st + row * PBY + qid * 4 + jb;
                const char* p1 = st + (row + 8) * PBY + qid * 4 + jb;
                af[mi][0] = LDU32(p0);
                af[mi][1] = LDU32(p1);
                af[mi][2] = LDU32(p0 + 16);
                af[mi][3] = LDU32(p1 + 16);
            }
#pragma unroll
            for (int ni = 0; ni < 4; ni++) {
                int col = wn * 32 + ni * 8 + gid;
                const char* p = stB + col * PBY + qid * 4 + jb;
                bf[ni][0] = LDU32(p);
                bf[ni][1] = LDU32(p + 16);
            }
#pragma unroll
            for (int mi = 0; mi < 4; mi++)
#pragma unroll
                for (int ni = 0; ni < 4; ni++)
                    MMA_F16(acc[mi][ni], af[mi][0], af[mi][1], af[mi][2],
                            af[mi][3], bf[ni][0], bf[ni][1]);
        }
        buf = (buf + 1) % 3;
    }
#undef LOAD_STAGE

    // epilogue
    int bn = blockIdx.x * 128;
#pragma unroll
    for (int mi = 0; mi < 4; mi++) {
        int r0 = blockIdx.y * 128 + wm * 64 + mi * 16 + gid;
        int r1 = r0 + 8;
#pragma unroll
        for (int ni = 0; ni < 4; ni++) {
            int col = bn + wn * 32 + ni * 8 + 2 * qid;
            float2 v0 = make_float2(acc[mi][ni][0], acc[mi][ni][1]);
            float2 v1 = make_float2(acc[mi][ni][2], acc[mi][ni][3]);
            if (qkv_mode) {
                int which = col >> 10;
                int cc = col & 1023;
                int hh = cc >> 6, aa = cc & 63;
                int bb = r0 >> 11;
                int s0r = r0 & 2047, s1r = r1 & 2047;
                int hb_ = hh * B + bb;
                size_t d0 = (((size_t)hb_ * S + s0r) * A + aa);
                size_t d1 = (((size_t)hb_ * S + s1r) * A + aa);
                if (which == 0) {
                    *(uint32_t*)(qd + d0) = h2pack(v0.x, v0.y);
                    *(uint32_t*)(qd + d1) = h2pack(v1.x, v1.y);
                } else if (which == 1) {
                    *(float2*)(kd + d0) = v0;
                    *(float2*)(kd + d1) = v1;
                    *(uint32_t*)(khd + d0) = h2pack(v0.x, v0.y);
                    *(uint32_t*)(khd + d1) = h2pack(v1.x, v1.y);
                } else {
                    *(float2*)(vd + d0) = v0;
                    *(float2*)(vd + d1) = v1;
                    size_t vt0 = ((size_t)hb_ * A + aa) * S;
                    vtd[vt0 + s0r]     = __float2half_rn(v0.x);
                    vtd[vt0 + S + s0r] = __float2half_rn(v0.y);
                    vtd[vt0 + s1r]     = __float2half_rn(v1.x);
                    vtd[vt0 + S + s1r] = __float2half_rn(v1.y);
                }
            } else {
                if (bias) {
                    float2 bv = *(const float2*)(bias + col);
                    v0.x += bv.x; v0.y += bv.y; v1.x += bv.x; v1.y += bv.y;
                }
                if (resid) {
                    float2 q0 = *(const float2*)(resid + (size_t)r0 * Nd + col);
                    float2 q1 = *(const float2*)(resid + (size_t)r1 * Nd + col);
                    v0.x += q0.x; v0.y += q0.y; v1.x += q1.x; v1.y += q1.y;
                }
                if (do_relu) {
                    v0.x = fmaxf(v0.x, 0.f); v0.y = fmaxf(v0.y, 0.f);
                    v1.x = fmaxf(v1.x, 0.f); v1.y = fmaxf(v1.y, 0.f);
                }
                if (Cg) {
                    *(float2*)(Cg + (size_t)r0 * Nd + col) = v0;
                    *(float2*)(Cg + (size_t)r1 * Nd + col) = v1;
                }
                if (Cg16) {
                    *(uint32_t*)(Cg16 + (size_t)r0 * Nd + col) = h2pack(v0.x, v0.y);
                    *(uint32_t*)(Cg16 + (size_t)r1 * Nd + col) = h2pack(v1.x, v1.y);
                }
            }
        }
    }
}

// ---------------- fp16 tensor-core flash attention --------------------------------
#define APB 144
#define ATT_SMEM ((128 + 128 + 64 + 64) * APB)

__global__ __launch_bounds__(256, 2)
void k_attn(const __half* __restrict__ Qg, const __half* __restrict__ Khg,
            const __half* __restrict__ Vtg, __half* __restrict__ attn_out) {
    extern __shared__ char sma[];
    char* Qs = sma;                    // [128][144]
    char* Ps = Qs + 128 * APB;         // [128][144]
    char* Ks = Ps + 128 * APB;         // [64][144]  key x dim
    char* Vt = Ks + 64 * APB;          // [64][144]  dim x key

    int tid = threadIdx.x, lane = tid & 31, wid = tid >> 5;
    int gid = lane >> 2, qid = lane & 3;
    int hb = blockIdx.y, qt = blockIdx.x;
    int h = hb / B, b = hb - h * B;
    int q0 = qt * 128;

    // Q tile: 128 rows x 128 B = 1024 chunks
    const uint4* Q4 = (const uint4*)(Qg + ((size_t)hb * S + q0) * A);
#pragma unroll
    for (int j = 0; j < 4; j++) {
        int i = tid + j * 256;
        int r = i >> 3, c = i & 7;
        *(uint4*)(Qs + r * APB + c * 16) = Q4[i];
    }

    int wr = wid * 16;
    int r0g = q0 + wr + gid, r1g = r0g + 8;
    float m0 = -INFINITY, m1 = -INFINITY, l0 = 0.f, l1 = 0.f;
    float o[8][4];
#pragma unroll
    for (int nt = 0; nt < 8; nt++)
#pragma unroll
        for (int c = 0; c < 4; c++) o[nt][c] = 0.f;

    const float scale = 0.03125f;
    int ntl = 2 * qt + 2;
    const uint4* K4 = (const uint4*)(Khg + (size_t)hb * S * A);
    const uint4* V4 = (const uint4*)(Vtg + (size_t)hb * A * S);

    for (int t = 0; t < ntl; t++) {
        int k0 = t * 64;
        __syncthreads();
        // K tile + V tile: 512 chunks each, 2 per thread per tile
#pragma unroll
        for (int j = 0; j < 2; j++) {
            int i = tid + j * 256;
            int r = i >> 3, c = i & 7;
            *(uint4*)(Ks + r * APB + c * 16) = K4[(size_t)(k0 + r) * 8 + c];
            *(uint4*)(Vt + r * APB + c * 16) = V4[(size_t)r * (S / 8) + (k0 >> 3) + c];
        }
        __syncthreads();

        if (k0 <= q0 + wr + 15) {
            // ---- QK^T (k = 64 dims -> 4 x k16) ----
            float sa[8][4];
#pragma unroll
            for (int nt = 0; nt < 8; nt++)
#pragma unroll
                for (int c = 0; c < 4; c++) sa[nt][c] = 0.f;
#pragma unroll
            for (int j = 0; j < 4; j++) {
                int jb = j * 32;
                const char* pa0 = Qs + (wr + gid) * APB + qid * 4 + jb;
                const char* pa1 = Qs + (wr + gid + 8) * APB + qid * 4 + jb;
                unsigned a0 = LDU32(pa0), a1 = LDU32(pa1);
                unsigned a2 = LDU32(pa0 + 16), a3 = LDU32(pa1 + 16);
#pragma unroll
                for (int nt = 0; nt < 8; nt++) {
                    const char* pb = Ks + (nt * 8 + gid) * APB + qid * 4 + jb;
                    MMA_F16(sa[nt], a0, a1, a2, a3, LDU32(pb), LDU32(pb + 16));
                }
            }
            // ---- scale + mask + online softmax (fp32) ----
            float mx0 = -INFINITY, mx1 = -INFINITY;
#pragma unroll
            for (int nt = 0; nt < 8; nt++) {
                int colb = k0 + nt * 8 + 2 * qid;
                sa[nt][0] = (colb     <= r0g) ? sa[nt][0] * scale : -INFINITY;
                sa[nt][1] = (colb + 1 <= r0g) ? sa[nt][1] * scale : -INFINITY;
                sa[nt][2] = (colb     <= r1g) ? sa[nt][2] * scale : -INFINITY;
                sa[nt][3] = (colb + 1 <= r1g) ? sa[nt][3] * scale : -INFINITY;
                mx0 = fmaxf(mx0, fmaxf(sa[nt][0], sa[nt][1]));
                mx1 = fmaxf(mx1, fmaxf(sa[nt][2], sa[nt][3]));
            }
            mx0 = fmaxf(mx0, __shfl_xor_sync(0xffffffff, mx0, 1));
            mx0 = fmaxf(mx0, __shfl_xor_sync(0xffffffff, mx0, 2));
            mx1 = fmaxf(mx1, __shfl_xor_sync(0xffffffff, mx1, 1));
            mx1 = fmaxf(mx1, __shfl_xor_sync(0xffffffff, mx1, 2));
            float mn0 = fmaxf(m0, mx0), mn1 = fmaxf(m1, mx1);
            float al0 = __expf(m0 - mn0), al1 = __expf(m1 - mn1);
            float sum0 = 0.f, sum1 = 0.f;
#pragma unroll
            for (int nt = 0; nt < 8; nt++) {
                sa[nt][0] = __expf(sa[nt][0] - mn0); sum0 += sa[nt][0];
                sa[nt][1] = __expf(sa[nt][1] - mn0); sum0 += sa[nt][1];
                sa[nt][2] = __expf(sa[nt][2] - mn1); sum1 += sa[nt][2];
                sa[nt][3] = __expf(sa[nt][3] - mn1); sum1 += sa[nt][3];
            }
            sum0 += __shfl_xor_sync(0xffffffff, sum0, 1);
            sum0 += __shfl_xor_sync(0xffffffff, sum0, 2);
            sum1 += __shfl_xor_sync(0xffffffff, sum1, 1);
            sum1 += __shfl_xor_sync(0xffffffff, sum1, 2);
            l0 = l0 * al0 + sum0;  m0 = mn0;
            l1 = l1 * al1 + sum1;  m1 = mn1;
#pragma unroll
            for (int nt = 0; nt < 8; nt++) {
                o[nt][0] *= al0; o[nt][1] *= al0;
                o[nt][2] *= al1; o[nt][3] *= al1;
            }
            // ---- P -> smem (half, warp-private rows) ----
#pragma unroll
            for (int nt = 0; nt < 8; nt++) {
                *(uint32_t*)(Ps + (wr + gid) * APB + (nt * 8 + 2 * qid) * 2) =
                    h2pack(sa[nt][0], sa[nt][1]);
                *(uint32_t*)(Ps + (wr + gid + 8) * APB + (nt * 8 + 2 * qid) * 2) =
                    h2pack(sa[nt][2], sa[nt][3]);
            }
            __syncwarp();
            // ---- PV (k = 64 keys -> 4 x k16) ----
#pragma unroll
            for (int j = 0; j < 4; j++) {
                int jb = j * 32;
                const char* pa0 = Ps + (wr + gid) * APB + qid * 4 + jb;
                const char* pa1 = Ps + (wr + gid + 8) * APB + qid * 4 + jb;
                unsigned a0 = LDU32(pa0), a1 = LDU32(pa1);
                unsigned a2 = LDU32(pa0 + 16), a3 = LDU32(pa1 + 16);
#pragma unroll
                for (int nt = 0; nt < 8; nt++) {
                    const char* pb = Vt + (nt * 8 + gid) * APB + qid * 4 + jb;
                    MMA_F16(o[nt], a0, a1, a2, a3, LDU32(pb), LDU32(pb + 16));
                }
            }
        }
    }

    // epilogue: /l, write half
    float il0 = 1.f / l0, il1 = 1.f / l1;
    int row0 = b * S + q0 + wr + gid;
    int row1 = row0 + 8;
#pragma unroll
    for (int nt = 0; nt < 8; nt++) {
        int col = h * A + nt * 8 + 2 * qid;
        *(uint32_t*)(attn_out + (size_t)row0 * E + col) =
            h2pack(o[nt][0] * il0, o[nt][1] * il0);
        *(uint32_t*)(attn_out + (size_t)row1 * E + col) =
            h2pack(o[nt][2] * il1, o[nt][3] * il1);
    }
}

// ---------------- LayerNorm (optional fp16 second output) ------------------------
__global__ __launch_bounds__(256)
void k_ln(const float* __restrict__ a, const float* __restrict__ b,
          const float* __restrict__ gg, const float* __restrict__ bb,
          float* __restrict__ o, __half* __restrict__ o16) {
    __shared__ float red[16];
    __shared__ float s_mu, s_rstd;
    int row = blockIdx.x;
    int t = threadIdx.x;
    float4 x = ((const float4*)(a + (size_t)row * E))[t];
    if (b) {
        float4 y = ((const float4*)(b + (size_t)row * E))[t];
        x.x += y.x; x.y += y.y; x.z += y.z; x.w += y.w;
    }
    float sum = x.x + x.y + x.z + x.w;
    float sq  = x.x*x.x + x.y*x.y + x.z*x.z + x.w*x.w;
#pragma unroll
    for (int off = 16; off; off >>= 1) {
        sum += __shfl_xor_sync(0xffffffff, sum, off);
        sq  += __shfl_xor_sync(0xffffffff, sq,  off);
    }
    if ((t & 31) == 0) { red[t >> 5] = sum; red[8 + (t >> 5)] = sq; }
    __syncthreads();
    if (t == 0) {
        float ts = 0.f, tq = 0.f;
#pragma unroll
        for (int i = 0; i < 8; i++) { ts += red[i]; tq += red[8 + i]; }
        float mu = ts * (1.f / E);
        float var = tq * (1.f / E) - mu * mu;
        s_mu = mu; s_rstd = rsqrtf(var + 1e-5f);
    }
    __syncthreads();
    float mu = s_mu, rstd = s_rstd;
    float4 g4 = ((const float4*)gg)[t];
    float4 b4 = ((const float4*)bb)[t];
    float4 rr;
    rr.x = (x.x - mu) * rstd * g4.x + b4.x;
    rr.y = (x.y - mu) * rstd * g4.y + b4.y;
    rr.z = (x.z - mu) * rstd * g4.z + b4.z;
    rr.w = (x.w - mu) * rstd * g4.w + b4.w;
    ((float4*)(o + (size_t)row * E))[t] = rr;
    if (o16) {
        uint2 hh;
        hh.x = h2pack(rr.x, rr.y);
        hh.y = h2pack(rr.z, rr.w);
        ((uint2*)(o16 + (size_t)row * E))[t] = hh;
    }
}

// ---------------- launch ----------------------------------------------------------
extern "C" void kernel_launch(void* const* d_in, const int* in_sizes, int n_in,
                              void* d_out, int out_size) {
    const float* emb    = (const float*)d_in[0];
    const float* pos    = (const float*)d_in[1];
    const float* Wq     = (const float*)d_in[2];
    const float* Wk     = (const float*)d_in[3];
    const float* Wv     = (const float*)d_in[4];
    const float* Wproj  = (const float*)d_in[5];
    const float* W1     = (const float*)d_in[6];
    const float* b1     = (const float*)d_in[7];
    const float* W2     = (const float*)d_in[8];
    const float* b2     = (const float*)d_in[9];
    const float* gattn  = (const float*)d_in[10];
    const float* beattn = (const float*)d_in[11];
    const float* gffn   = (const float*)d_in[12];
    const float* beffn  = (const float*)d_in[13];
    const float* gout   = (const float*)d_in[14];
    const float* beout  = (const float*)d_in[15];

    float* out  = (float*)d_out;
    float* Kout = out + (size_t)M * E;
    float* Vout = out + (size_t)2 * M * E;

    float *px, *pqkv, *pmha, *pff, *pffout;
    __half *px16, *pw, *pwp, *pw1, *pw2, *pq16, *pkh, *pvt, *pattn16, *pmha16, *phid16;
    cudaGetSymbolAddress((void**)&px,     g_x);
    cudaGetSymbolAddress((void**)&px16,   g_x16);
    cudaGetSymbolAddress((void**)&pw,     g_wqkvT);
    cudaGetSymbolAddress((void**)&pwp,    g_wpT);
    cudaGetSymbolAddress((void**)&pw1,    g_w1T);
    cudaGetSymbolAddress((void**)&pw2,    g_w2T);
    cudaGetSymbolAddress((void**)&pqkv,   g_qkv);
    cudaGetSymbolAddress((void**)&pq16,   g_q16);
    cudaGetSymbolAddress((void**)&pkh,    g_kh);
    cudaGetSymbolAddress((void**)&pvt,    g_vt);
    cudaGetSymbolAddress((void**)&pattn16,g_attn16);
    cudaGetSymbolAddress((void**)&pmha,   g_mha);
    cudaGetSymbolAddress((void**)&pmha16, g_mha16);
    cudaGetSymbolAddress((void**)&phid16, g_hid16);
    cudaGetSymbolAddress((void**)&pff,    g_ff);
    cudaGetSymbolAddress((void**)&pffout, g_ffout);

    cudaFuncSetAttribute(k_attn, cudaFuncAttributeMaxDynamicSharedMemorySize,
                         ATT_SMEM);
    cudaFuncSetAttribute(k_gemm_h, cudaFuncAttributeMaxDynamicSharedMemorySize,
                         GEMM_SMEM);

    dim3 trb(32, 8);
    // 1: x = emb + pos
    k_add<<<(M * E / 4) / 256, 256>>>((const float4*)emb, (const float4*)pos,
                                      (float4*)px, (uint2*)px16);
    // 2-5: QKV + proj weight transposes (fp16 [N][K])
    k_tr<<<dim3(A/32, E/32, H), trb>>>(Wq, pw,                 E, A, (long)E*A, (long)A*E);
    k_tr<<<dim3(A/32, E/32, H), trb>>>(Wk, pw + (size_t)E*E,   E, A, (long)E*A, (long)A*E);
    k_tr<<<dim3(A/32, E/32, H), trb>>>(Wv, pw + (size_t)2*E*E, E, A, (long)E*A, (long)A*E);
    k_tr<<<dim3(E/32, E/32, 1), trb>>>(Wproj, pwp, E, E, 0, 0);
    // 6: QKV GEMM (profiled slot) -> Q/K half, V^T half, K/V fp32 d_out
    k_gemm_h<<<dim3(NQKV/128, M/128), 256, GEMM_SMEM>>>(
        px16, pw, nullptr, nullptr, NQKV, E, nullptr, nullptr, 0, 1,
        pq16, Kout, Vout, pkh, pvt);
    // 7-8: FFN weight transposes
    k_tr<<<dim3(FFD/32, E/32, 1), trb>>>(W1, pw1, E, FFD, 0, 0);
    k_tr<<<dim3(E/32, FFD/32, 1), trb>>>(W2, pw2, FFD, E, 0, 0);
    // 9: fp16 flash attention
    k_attn<<<dim3(S/128, H*B), 256, ATT_SMEM>>>(pq16, pkh, pvt, pattn16);
    // 10: proj + residual(x fp32) -> fp32
    k_gemm_h<<<dim3(E/128, M/128), 256, GEMM_SMEM>>>(
        pattn16, pwp, pqkv, nullptr, E, E, nullptr, px, 0, 0,
        nullptr, nullptr, nullptr, nullptr, nullptr);
    // 11: LN -> mha fp32 + fp16
    k_ln<<<M, 256>>>(pqkv, nullptr, gattn, beattn, pmha, pmha16);
    // 12: FFN1 (+b1) -> fp16 hidden only
    k_gemm_h<<<dim3(FFD/128, M/128), 256, GEMM_SMEM>>>(
        pmha16, pw1, nullptr, phid16, FFD, E, b1, nullptr, 0, 0,
        nullptr, nullptr, nullptr, nullptr, nullptr);
    // 13: FFN2 (+b2, relu) -> fp32
    k_gemm_h<<<dim3(E/128, M/128), 256, GEMM_SMEM>>>(
        phid16, pw2, pff, nullptr, E, FFD, b2, nullptr, 1, 0,
        nullptr, nullptr, nullptr, nullptr, nullptr);
    // 14-15: LNs
    k_ln<<<M, 256>>>(pmha, pff, gffn, beffn, pffout, nullptr);
    k_ln<<<M, 256>>>(pmha, pffout, gout, beout, out, nullptr);
}

// round 14
// speedup vs baseline: 1.7914x; 1.0172x over previous
#include <cuda_runtime.h>
#include <cuda_fp16.h>
#include <math.h>
#include <stdint.h>

// Problem constants
#define E   1024
#define A   64
#define H   16
#define FFD 4096
#define B   2
#define S   2048
#define M   (B*S)
#define NQKV (3*E)

// ---------------- scratch (device globals) -----------------------------------
__device__ float  g_x[M*E];
__device__ __half g_x16[M*E];
__device__ __half g_wqkvT[NQKV*E];
__device__ __half g_wpT[E*E];
__device__ __half g_w1T[FFD*E];
__device__ __half g_w2T[E*FFD];
__device__ float  g_qkv[M*E];
__device__ __half g_q16[M*E];
__device__ __half g_kh[M*E];
__device__ __half g_vt[M*E];
__device__ __half g_attn16[M*E];
__device__ float  g_mha[M*E];
__device__ __half g_mha16[M*E];
__device__ __half g_hid16[M*FFD];
__device__ float  g_ff[M*E];

// ---------------- helpers -------------------------------------------------------
__device__ __forceinline__ uint32_t smem_u32(const void* p) {
    uint32_t r;
    asm("{ .reg .u64 t; cvta.to.shared.u64 t, %1; cvt.u32.u64 %0, t; }"
        : "=r"(r) : "l"(p));
    return r;
}
__device__ __forceinline__ uint32_t h2pack(float x, float y) {
    __half2 h = __floats2half2_rn(x, y);
    return *(uint32_t*)&h;
}
#define CP16(dst, src) \
    asm volatile("cp.async.cg.shared.global [%0], [%1], 16;" \
                 :: "r"(dst), "l"(src) : "memory")
#define CP_COMMIT() asm volatile("cp.async.commit_group;" ::: "memory")
#define CP_WAIT(n)  asm volatile("cp.async.wait_group %0;" :: "n"(n) : "memory")
#define MMA_F16(d, a0,a1,a2,a3, b0,b1)                                        \
    asm volatile(                                                             \
        "mma.sync.aligned.m16n8k16.row.col.f32.f16.f16.f32 "                  \
        "{%0,%1,%2,%3}, {%4,%5,%6,%7}, {%8,%9}, {%0,%1,%2,%3};"               \
        : "+f"((d)[0]), "+f"((d)[1]), "+f"((d)[2]), "+f"((d)[3])              \
        : "r"(a0), "r"(a1), "r"(a2), "r"(a3), "r"(b0), "r"(b1))
#define LDU32(p) (*(const uint32_t*)(p))

// ---------------- x = emb + pos (fp32 + fp16 copy) -------------------------------
__global__ void k_add(const float4* __restrict__ a, const float4* __restrict__ b,
                      float4* __restrict__ o, uint2* __restrict__ o16) {
    int i = blockIdx.x * blockDim.x + threadIdx.x;
    float4 x = a[i], y = b[i];
    x.x += y.x; x.y += y.y; x.z += y.z; x.w += y.w;
    o[i] = x;
    uint2 h;
    h.x = h2pack(x.x, x.y);
    h.y = h2pack(x.z, x.w);
    o16[i] = h;
}

// ---------------- tiled transpose fp32 [R][C] -> fp16 [C][R], batched ------------
// in3/out3: optional 3-way source select (fused QKV transposes, z in [0,3H))
__global__ void k_tr(const float* __restrict__ in, __half* __restrict__ out,
                     int R, int C, long ibs, long obs,
                     const float* __restrict__ in1, const float* __restrict__ in2,
                     int zsplit) {
    __shared__ float t[32][33];
    int z = blockIdx.z;
    const float* base = in;
    if (zsplit > 0) {
        int wsel = z / zsplit;
        base = (wsel == 0) ? in : (wsel == 1) ? in1 : in2;
        z = z - wsel * zsplit;
    }
    const float* ip = base + (size_t)z * ibs;
    __half* op = out + (size_t)blockIdx.z * obs;
    int c0 = blockIdx.x * 32, r0 = blockIdx.y * 32;
    int tx = threadIdx.x, ty = threadIdx.y;
#pragma unroll
    for (int j = 0; j < 4; j++)
        t[ty + j*8][tx] = ip[(size_t)(r0 + ty + j*8) * C + c0 + tx];
    __syncthreads();
#pragma unroll
    for (int j = 0; j < 4; j++)
        op[(size_t)(c0 + ty + j*8) * R + r0 + tx] = __float2half_rn(t[tx][ty + j*8]);
}

// ---------------- fp16 mma GEMM, cp.async 3-stage --------------------------------
#define PBY 80
#define STG_B (256 * PBY)
#define GEMM_SMEM (3 * STG_B)

__global__ __launch_bounds__(256, 2)
void k_gemm_h(const __half* __restrict__ Ag, const __half* __restrict__ BTg,
              float* __restrict__ Cg, __half* __restrict__ Cg16,
              int Nd, int Kd,
              const float* __restrict__ bias, const float* __restrict__ resid,
              int do_relu, int qkv_mode,
              __half* __restrict__ qd, float* __restrict__ kd,
              float* __restrict__ vd, __half* __restrict__ khd,
              __half* __restrict__ vtd) {
    extern __shared__ char smh[];
    uint32_t sb = smem_u32(smh);

    int tid = threadIdx.x;
    int lane = tid & 31, wid = tid >> 5;
    int wm = wid & 1, wn = wid >> 1;
    int gid = lane >> 2, qid = lane & 3;

    const __half* Ab = Ag + (size_t)blockIdx.y * 128 * Kd;
    const __half* Bb = BTg + (size_t)blockIdx.x * 128 * Kd;

    int cr = tid >> 2;
    int co = tid & 3;

    float acc[4][4][4];
#pragma unroll
    for (int i = 0; i < 4; i++)
#pragma unroll
        for (int j = 0; j < 4; j++)
#pragma unroll
            for (int r = 0; r < 4; r++) acc[i][j][r] = 0.f;

    int nk = Kd >> 5;

#define LOAD_STAGE(s, k0)                                                     \
    do {                                                                      \
        uint32_t A0 = sb + (s) * STG_B;                                       \
        uint32_t B0 = A0 + 128 * PBY;                                         \
        CP16(A0 + cr * PBY + co * 16,        Ab + (size_t)cr * Kd + (k0) + co * 8); \
        CP16(A0 + (cr + 64) * PBY + co * 16, Ab + (size_t)(cr + 64) * Kd + (k0) + co * 8); \
        CP16(B0 + cr * PBY + co * 16,        Bb + (size_t)cr * Kd + (k0) + co * 8); \
        CP16(B0 + (cr + 64) * PBY + co * 16, Bb + (size_t)(cr + 64) * Kd + (k0) + co * 8); \
        CP_COMMIT();                                                          \
    } while (0)

    LOAD_STAGE(0, 0);
    LOAD_STAGE(1, 32);

    int buf = 0;
    for (int kc = 0; kc < nk; kc++) {
        if (kc + 2 < nk) { CP_WAIT(1); } else { CP_WAIT(0); }
        __syncthreads();
        if (kc + 2 < nk) {
            int s = (kc + 2) % 3;
            LOAD_STAGE(s, (kc + 2) * 32);
        }
        const char* st = smh + buf * STG_B;
        const char* stB = st + 128 * PBY;
#pragma unroll
        for (int j = 0; j < 2; j++) {
            int jb = j * 32;
            unsigned af[4][4], bf[4][2];
#pragma unroll
            for (int mi = 0; mi < 4; mi++) {
                int row = wm * 64 + mi * 16 + gid;
                const char* p0 = st + row * PBY + qid * 4 + jb;
                const char* p1 = st + (row + 8) * PBY + qid * 4 + jb;
                af[mi][0] = LDU32(p0);
                af[mi][1] = LDU32(p1);
                af[mi][2] = LDU32(p0 + 16);
                af[mi][3] = LDU32(p1 + 16);
            }
#pragma unroll
            for (int ni = 0; ni < 4; ni++) {
                int col = wn * 32 + ni * 8 + gid;
                const char* p = stB + col * PBY + qid * 4 + jb;
                bf[ni][0] = LDU32(p);
                bf[ni][1] = LDU32(p + 16);
            }
#pragma unroll
            for (int mi = 0; mi < 4; mi++)
#pragma unroll
                for (int ni = 0; ni < 4; ni++)
                    MMA_F16(acc[mi][ni], af[mi][0], af[mi][1], af[mi][2],
                            af[mi][3], bf[ni][0], bf[ni][1]);
        }
        buf = (buf + 1) % 3;
    }
#undef LOAD_STAGE

    // epilogue
    int bn = blockIdx.x * 128;
#pragma unroll
    for (int mi = 0; mi < 4; mi++) {
        int r0 = blockIdx.y * 128 + wm * 64 + mi * 16 + gid;
        int r1 = r0 + 8;
#pragma unroll
        for (int ni = 0; ni < 4; ni++) {
            int col = bn + wn * 32 + ni * 8 + 2 * qid;
            float2 v0 = make_float2(acc[mi][ni][0], acc[mi][ni][1]);
            float2 v1 = make_float2(acc[mi][ni][2], acc[mi][ni][3]);
            if (qkv_mode) {
                int which = col >> 10;
                int cc = col & 1023;
                int hh = cc >> 6, aa = cc & 63;
                int bb = r0 >> 11;
                int s0r = r0 & 2047, s1r = r1 & 2047;
                int hb_ = hh * B + bb;
                size_t d0 = (((size_t)hb_ * S + s0r) * A + aa);
                size_t d1 = (((size_t)hb_ * S + s1r) * A + aa);
                if (which == 0) {
                    *(uint32_t*)(qd + d0) = h2pack(v0.x, v0.y);
                    *(uint32_t*)(qd + d1) = h2pack(v1.x, v1.y);
                } else if (which == 1) {
                    *(float2*)(kd + d0) = v0;
                    *(float2*)(kd + d1) = v1;
                    *(uint32_t*)(khd + d0) = h2pack(v0.x, v0.y);
                    *(uint32_t*)(khd + d1) = h2pack(v1.x, v1.y);
                } else {
                    *(float2*)(vd + d0) = v0;
                    *(float2*)(vd + d1) = v1;
                    size_t vt0 = ((size_t)hb_ * A + aa) * S;
                    vtd[vt0 + s0r]     = __float2half_rn(v0.x);
                    vtd[vt0 + S + s0r] = __float2half_rn(v0.y);
                    vtd[vt0 + s1r]     = __float2half_rn(v1.x);
                    vtd[vt0 + S + s1r] = __float2half_rn(v1.y);
                }
            } else {
                if (bias) {
                    float2 bv = *(const float2*)(bias + col);
                    v0.x += bv.x; v0.y += bv.y; v1.x += bv.x; v1.y += bv.y;
                }
                if (resid) {
                    float2 q0 = *(const float2*)(resid + (size_t)r0 * Nd + col);
                    float2 q1 = *(const float2*)(resid + (size_t)r1 * Nd + col);
                    v0.x += q0.x; v0.y += q0.y; v1.x += q1.x; v1.y += q1.y;
                }
                if (do_relu) {
                    v0.x = fmaxf(v0.x, 0.f); v0.y = fmaxf(v0.y, 0.f);
                    v1.x = fmaxf(v1.x, 0.f); v1.y = fmaxf(v1.y, 0.f);
                }
                if (Cg) {
                    *(float2*)(Cg + (size_t)r0 * Nd + col) = v0;
                    *(float2*)(Cg + (size_t)r1 * Nd + col) = v1;
                }
                if (Cg16) {
                    *(uint32_t*)(Cg16 + (size_t)r0 * Nd + col) = h2pack(v0.x, v0.y);
                    *(uint32_t*)(Cg16 + (size_t)r1 * Nd + col) = h2pack(v1.x, v1.y);
                }
            }
        }
    }
}

// ---------------- fp16 tensor-core flash attention --------------------------------
#define APB 144
#define ATT_SMEM ((128 + 128 + 64 + 64) * APB)

__global__ __launch_bounds__(256, 2)
void k_attn(const __half* __restrict__ Qg, const __half* __restrict__ Khg,
            const __half* __restrict__ Vtg, __half* __restrict__ attn_out) {
    extern __shared__ char sma[];
    char* Qs = sma;
    char* Ps = Qs + 128 * APB;
    char* Ks = Ps + 128 * APB;
    char* Vt = Ks + 64 * APB;

    int tid = threadIdx.x, lane = tid & 31, wid = tid >> 5;
    int gid = lane >> 2, qid = lane & 3;
    int hb = blockIdx.y;
    int qt = gridDim.x - 1 - blockIdx.x;   // big tiles first (load balance)
    int h = hb / B, b = hb - h * B;
    int q0 = qt * 128;

    const uint4* Q4 = (const uint4*)(Qg + ((size_t)hb * S + q0) * A);
#pragma unroll
    for (int j = 0; j < 4; j++) {
        int i = tid + j * 256;
        int r = i >> 3, c = i & 7;
        *(uint4*)(Qs + r * APB + c * 16) = Q4[i];
    }

    int wr = wid * 16;
    int r0g = q0 + wr + gid, r1g = r0g + 8;
    float m0 = -INFINITY, m1 = -INFINITY, l0 = 0.f, l1 = 0.f;
    float o[8][4];
#pragma unroll
    for (int nt = 0; nt < 8; nt++)
#pragma unroll
        for (int c = 0; c < 4; c++) o[nt][c] = 0.f;

    const float scale = 0.03125f;
    int ntl = 2 * qt + 2;
    const uint4* K4 = (const uint4*)(Khg + (size_t)hb * S * A);
    const uint4* V4 = (const uint4*)(Vtg + (size_t)hb * A * S);

    for (int t = 0; t < ntl; t++) {
        int k0 = t * 64;
        __syncthreads();
#pragma unroll
        for (int j = 0; j < 2; j++) {
            int i = tid + j * 256;
            int r = i >> 3, c = i & 7;
            *(uint4*)(Ks + r * APB + c * 16) = K4[(size_t)(k0 + r) * 8 + c];
            *(uint4*)(Vt + r * APB + c * 16) = V4[(size_t)r * (S / 8) + (k0 >> 3) + c];
        }
        __syncthreads();

        if (k0 <= q0 + wr + 15) {
            float sa[8][4];
#pragma unroll
            for (int nt = 0; nt < 8; nt++)
#pragma unroll
                for (int c = 0; c < 4; c++) sa[nt][c] = 0.f;
#pragma unroll
            for (int j = 0; j < 4; j++) {
                int jb = j * 32;
                const char* pa0 = Qs + (wr + gid) * APB + qid * 4 + jb;
                const char* pa1 = Qs + (wr + gid + 8) * APB + qid * 4 + jb;
                unsigned a0 = LDU32(pa0), a1 = LDU32(pa1);
                unsigned a2 = LDU32(pa0 + 16), a3 = LDU32(pa1 + 16);
#pragma unroll
                for (int nt = 0; nt < 8; nt++) {
                    const char* pb = Ks + (nt * 8 + gid) * APB + qid * 4 + jb;
                    MMA_F16(sa[nt], a0, a1, a2, a3, LDU32(pb), LDU32(pb + 16));
                }
            }
            float mx0 = -INFINITY, mx1 = -INFINITY;
#pragma unroll
            for (int nt = 0; nt < 8; nt++) {
                int colb = k0 + nt * 8 + 2 * qid;
                sa[nt][0] = (colb     <= r0g) ? sa[nt][0] * scale : -INFINITY;
                sa[nt][1] = (colb + 1 <= r0g) ? sa[nt][1] * scale : -INFINITY;
                sa[nt][2] = (colb     <= r1g) ? sa[nt][2] * scale : -INFINITY;
                sa[nt][3] = (colb + 1 <= r1g) ? sa[nt][3] * scale : -INFINITY;
                mx0 = fmaxf(mx0, fmaxf(sa[nt][0], sa[nt][1]));
                mx1 = fmaxf(mx1, fmaxf(sa[nt][2], sa[nt][3]));
            }
            mx0 = fmaxf(mx0, __shfl_xor_sync(0xffffffff, mx0, 1));
            mx0 = fmaxf(mx0, __shfl_xor_sync(0xffffffff, mx0, 2));
            mx1 = fmaxf(mx1, __shfl_xor_sync(0xffffffff, mx1, 1));
            mx1 = fmaxf(mx1, __shfl_xor_sync(0xffffffff, mx1, 2));
            float mn0 = fmaxf(m0, mx0), mn1 = fmaxf(m1, mx1);
            float al0 = __expf(m0 - mn0), al1 = __expf(m1 - mn1);
            float sum0 = 0.f, sum1 = 0.f;
#pragma unroll
            for (int nt = 0; nt < 8; nt++) {
                sa[nt][0] = __expf(sa[nt][0] - mn0); sum0 += sa[nt][0];
                sa[nt][1] = __expf(sa[nt][1] - mn0); sum0 += sa[nt][1];
                sa[nt][2] = __expf(sa[nt][2] - mn1); sum1 += sa[nt][2];
                sa[nt][3] = __expf(sa[nt][3] - mn1); sum1 += sa[nt][3];
            }
            sum0 += __shfl_xor_sync(0xffffffff, sum0, 1);
            sum0 += __shfl_xor_sync(0xffffffff, sum0, 2);
            sum1 += __shfl_xor_sync(0xffffffff, sum1, 1);
            sum1 += __shfl_xor_sync(0xffffffff, sum1, 2);
            l0 = l0 * al0 + sum0;  m0 = mn0;
            l1 = l1 * al1 + sum1;  m1 = mn1;
#pragma unroll
            for (int nt = 0; nt < 8; nt++) {
                o[nt][0] *= al0; o[nt][1] *= al0;
                o[nt][2] *= al1; o[nt][3] *= al1;
            }
#pragma unroll
            for (int nt = 0; nt < 8; nt++) {
                *(uint32_t*)(Ps + (wr + gid) * APB + (nt * 8 + 2 * qid) * 2) =
                    h2pack(sa[nt][0], sa[nt][1]);
                *(uint32_t*)(Ps + (wr + gid + 8) * APB + (nt * 8 + 2 * qid) * 2) =
                    h2pack(sa[nt][2], sa[nt][3]);
            }
            __syncwarp();
#pragma unroll
            for (int j = 0; j < 4; j++) {
                int jb = j * 32;
                const char* pa0 = Ps + (wr + gid) * APB + qid * 4 + jb;
                const char* pa1 = Ps + (wr + gid + 8) * APB + qid * 4 + jb;
                unsigned a0 = LDU32(pa0), a1 = LDU32(pa1);
                unsigned a2 = LDU32(pa0 + 16), a3 = LDU32(pa1 + 16);
#pragma unroll
                for (int nt = 0; nt < 8; nt++) {
                    const char* pb = Vt + (nt * 8 + gid) * APB + qid * 4 + jb;
                    MMA_F16(o[nt], a0, a1, a2, a3, LDU32(pb), LDU32(pb + 16));
                }
            }
        }
    }

    float il0 = 1.f / l0, il1 = 1.f / l1;
    int row0 = b * S + q0 + wr + gid;
    int row1 = row0 + 8;
#pragma unroll
    for (int nt = 0; nt < 8; nt++) {
        int col = h * A + nt * 8 + 2 * qid;
        *(uint32_t*)(attn_out + (size_t)row0 * E + col) =
            h2pack(o[nt][0] * il0, o[nt][1] * il0);
        *(uint32_t*)(attn_out + (size_t)row1 * E + col) =
            h2pack(o[nt][2] * il1, o[nt][3] * il1);
    }
}

// ---------------- LayerNorm (single; optional fp16 second output) ----------------
__device__ __forceinline__ float4 ln_row(float4 x, int t, const float* gg,
                                         const float* bb, float* red) {
    float sum = x.x + x.y + x.z + x.w;
    float sq  = x.x*x.x + x.y*x.y + x.z*x.z + x.w*x.w;
#pragma unroll
    for (int off = 16; off; off >>= 1) {
        sum += __shfl_xor_sync(0xffffffff, sum, off);
        sq  += __shfl_xor_sync(0xffffffff, sq,  off);
    }
    if ((t & 31) == 0) { red[t >> 5] = sum; red[8 + (t >> 5)] = sq; }
    __syncthreads();
    float ts = 0.f, tq = 0.f;
#pragma unroll
    for (int i = 0; i < 8; i++) { ts += red[i]; tq += red[8 + i]; }
    float mu = ts * (1.f / E);
    float rstd = rsqrtf(tq * (1.f / E) - mu * mu + 1e-5f);
    float4 g4 = ((const float4*)gg)[t];
    float4 b4 = ((const float4*)bb)[t];
    float4 rr;
    rr.x = (x.x - mu) * rstd * g4.x + b4.x;
    rr.y = (x.y - mu) * rstd * g4.y + b4.y;
    rr.z = (x.z - mu) * rstd * g4.z + b4.z;
    rr.w = (x.w - mu) * rstd * g4.w + b4.w;
    return rr;
}

__global__ __launch_bounds__(256)
void k_ln(const float* __restrict__ a, const float* __restrict__ b,
          const float* __restrict__ gg, const float* __restrict__ bb,
          float* __restrict__ o, __half* __restrict__ o16) {
    __shared__ float red[16];
    int row = blockIdx.x;
    int t = threadIdx.x;
    float4 x = ((const float4*)(a + (size_t)row * E))[t];
    if (b) {
        float4 y = ((const float4*)(b + (size_t)row * E))[t];
        x.x += y.x; x.y += y.y; x.z += y.z; x.w += y.w;
    }
    float4 rr = ln_row(x, t, gg, bb, red);
    ((float4*)(o + (size_t)row * E))[t] = rr;
    if (o16) {
        uint2 hh;
        hh.x = h2pack(rr.x, rr.y);
        hh.y = h2pack(rr.z, rr.w);
        ((uint2*)(o16 + (size_t)row * E))[t] = hh;
    }
}

// fused: ffout = LN(mha+ff, g_ffn); out = LN(mha+ffout, g_out)
__global__ __launch_bounds__(256)
void k_ln2(const float* __restrict__ mha, const float* __restrict__ ff,
           const float* __restrict__ g1, const float* __restrict__ b1v,
           const float* __restrict__ g2, const float* __restrict__ b2v,
           float* __restrict__ out) {
    __shared__ float red[16];
    int row = blockIdx.x;
    int t = threadIdx.x;
    float4 xm = ((const float4*)(mha + (size_t)row * E))[t];
    float4 xf = ((const float4*)(ff + (size_t)row * E))[t];
    float4 x1;
    x1.x = xm.x + xf.x; x1.y = xm.y + xf.y;
    x1.z = xm.z + xf.z; x1.w = xm.w + xf.w;
    float4 r1 = ln_row(x1, t, g1, b1v, red);
    __syncthreads();
    float4 x2;
    x2.x = xm.x + r1.x; x2.y = xm.y + r1.y;
    x2.z = xm.z + r1.z; x2.w = xm.w + r1.w;
    float4 r2 = ln_row(x2, t, g2, b2v, red);
    ((float4*)(out + (size_t)row * E))[t] = r2;
}

// ---------------- launch ----------------------------------------------------------
extern "C" void kernel_launch(void* const* d_in, const int* in_sizes, int n_in,
                              void* d_out, int out_size) {
    const float* emb    = (const float*)d_in[0];
    const float* pos    = (const float*)d_in[1];
    const float* Wq     = (const float*)d_in[2];
    const float* Wk     = (const float*)d_in[3];
    const float* Wv     = (const float*)d_in[4];
    const float* Wproj  = (const float*)d_in[5];
    const float* W1     = (const float*)d_in[6];
    const float* b1     = (const float*)d_in[7];
    const float* W2     = (const float*)d_in[8];
    const float* b2     = (const float*)d_in[9];
    const float* gattn  = (const float*)d_in[10];
    const float* beattn = (const float*)d_in[11];
    const float* gffn   = (const float*)d_in[12];
    const float* beffn  = (const float*)d_in[13];
    const float* gout   = (const float*)d_in[14];
    const float* beout  = (const float*)d_in[15];

    float* out  = (float*)d_out;
    float* Kout = out + (size_t)M * E;
    float* Vout = out + (size_t)2 * M * E;

    float *px, *pqkv, *pmha, *pff;
    __half *px16, *pw, *pwp, *pw1, *pw2, *pq16, *pkh, *pvt, *pattn16, *pmha16, *phid16;
    cudaGetSymbolAddress((void**)&px,     g_x);
    cudaGetSymbolAddress((void**)&px16,   g_x16);
    cudaGetSymbolAddress((void**)&pw,     g_wqkvT);
    cudaGetSymbolAddress((void**)&pwp,    g_wpT);
    cudaGetSymbolAddress((void**)&pw1,    g_w1T);
    cudaGetSymbolAddress((void**)&pw2,    g_w2T);
    cudaGetSymbolAddress((void**)&pqkv,   g_qkv);
    cudaGetSymbolAddress((void**)&pq16,   g_q16);
    cudaGetSymbolAddress((void**)&pkh,    g_kh);
    cudaGetSymbolAddress((void**)&pvt,    g_vt);
    cudaGetSymbolAddress((void**)&pattn16,g_attn16);
    cudaGetSymbolAddress((void**)&pmha,   g_mha);
    cudaGetSymbolAddress((void**)&pmha16, g_mha16);
    cudaGetSymbolAddress((void**)&phid16, g_hid16);
    cudaGetSymbolAddress((void**)&pff,    g_ff);

    cudaFuncSetAttribute(k_attn, cudaFuncAttributeMaxDynamicSharedMemorySize,
                         ATT_SMEM);
    cudaFuncSetAttribute(k_gemm_h, cudaFuncAttributeMaxDynamicSharedMemorySize,
                         GEMM_SMEM);

    dim3 trb(32, 8);
    // 1: x = emb + pos
    k_add<<<(M * E / 4) / 256, 256>>>((const float4*)emb, (const float4*)pos,
                                      (float4*)px, (uint2*)px16);
    // 2: fused QKV weight transpose (z = 3H)
    k_tr<<<dim3(A/32, E/32, 3*H), trb>>>(Wq, pw, E, A, (long)E*A, (long)A*E,
                                         Wk, Wv, H);
    // 3-5: proj/W1/W2 transposes
    k_tr<<<dim3(E/32, E/32, 1), trb>>>(Wproj, pwp, E, E, 0, 0, nullptr, nullptr, 0);
    k_tr<<<dim3(FFD/32, E/32, 1), trb>>>(W1, pw1, E, FFD, 0, 0, nullptr, nullptr, 0);
    k_tr<<<dim3(E/32, FFD/32, 1), trb>>>(W2, pw2, FFD, E, 0, 0, nullptr, nullptr, 0);
    // 6: QKV GEMM -> Q/K half, V^T half, K/V fp32 d_out
    k_gemm_h<<<dim3(NQKV/128, M/128), 256, GEMM_SMEM>>>(
        px16, pw, nullptr, nullptr, NQKV, E, nullptr, nullptr, 0, 1,
        pq16, Kout, Vout, pkh, pvt);
    // 7: fp16 flash attention (big tiles first)
    k_attn<<<dim3(S/128, H*B), 256, ATT_SMEM>>>(pq16, pkh, pvt, pattn16);
    // 8: proj + residual(x fp32) -> fp32
    k_gemm_h<<<dim3(E/128, M/128), 256, GEMM_SMEM>>>(
        pattn16, pwp, pqkv, nullptr, E, E, nullptr, px, 0, 0,
        nullptr, nullptr, nullptr, nullptr, nullptr);
    // 9: LN -> mha fp32 + fp16
    k_ln<<<M, 256>>>(pqkv, nullptr, gattn, beattn, pmha, pmha16);
    // 10: FFN1 (+b1) -> fp16 hidden
    k_gemm_h<<<dim3(FFD/128, M/128), 256, GEMM_SMEM>>>(
        pmha16, pw1, nullptr, phid16, FFD, E, b1, nullptr, 0, 0,
        nullptr, nullptr, nullptr, nullptr, nullptr);
    // 11: FFN2 (+b2, relu) -> fp32
    k_gemm_h<<<dim3(E/128, M/128), 256, GEMM_SMEM>>>(
        phid16, pw2, pff, nullptr, E, FFD, b2, nullptr, 1, 0,
        nullptr, nullptr, nullptr, nullptr, nullptr);
    // 12: fused double-LN -> encoded
    k_ln2<<<M, 256>>>(pmha, pff, gffn, beffn, gout, beout, out);
}

// round 15
// speedup vs baseline: 1.9612x; 1.0948x over previous
#include <cuda_runtime.h>
#include <cuda_fp16.h>
#include <math.h>
#include <stdint.h>

// Problem constants
#define E   1024
#define A   64
#define H   16
#define FFD 4096
#define B   2
#define S   2048
#define M   (B*S)
#define NQKV (3*E)

// ---------------- scratch (device globals) -----------------------------------
__device__ float  g_x[M*E];
__device__ __half g_x16[M*E];
__device__ __half g_wqkvT[NQKV*E];
__device__ __half g_wpT[E*E];
__device__ __half g_w1T[FFD*E];
__device__ __half g_w2T[E*FFD];
__device__ float  g_qkv[M*E];
__device__ __half g_q16[M*E];
__device__ __half g_kh[M*E];
__device__ __half g_vt[M*E];
__device__ __half g_attn16[M*E];
__device__ float  g_mha[M*E];
__device__ __half g_mha16[M*E];
__device__ __half g_hid16[M*FFD];
__device__ float  g_ff[M*E];

// ---------------- helpers -------------------------------------------------------
__device__ __forceinline__ uint32_t smem_u32(const void* p) {
    uint32_t r;
    asm("{ .reg .u64 t; cvta.to.shared.u64 t, %1; cvt.u32.u64 %0, t; }"
        : "=r"(r) : "l"(p));
    return r;
}
__device__ __forceinline__ uint32_t h2pack(float x, float y) {
    __half2 h = __floats2half2_rn(x, y);
    return *(uint32_t*)&h;
}
#define CP16(dst, src) \
    asm volatile("cp.async.cg.shared.global [%0], [%1], 16;" \
                 :: "r"(dst), "l"(src) : "memory")
#define CP_COMMIT() asm volatile("cp.async.commit_group;" ::: "memory")
#define CP_WAIT(n)  asm volatile("cp.async.wait_group %0;" :: "n"(n) : "memory")
#define MMA_F16(d, a0,a1,a2,a3, b0,b1)                                        \
    asm volatile(                                                             \
        "mma.sync.aligned.m16n8k16.row.col.f32.f16.f16.f32 "                  \
        "{%0,%1,%2,%3}, {%4,%5,%6,%7}, {%8,%9}, {%0,%1,%2,%3};"               \
        : "+f"((d)[0]), "+f"((d)[1]), "+f"((d)[2]), "+f"((d)[3])              \
        : "r"(a0), "r"(a1), "r"(a2), "r"(a3), "r"(b0), "r"(b1))
#define LDSM4(r0, r1, r2, r3, addr)                                           \
    asm volatile("ldmatrix.sync.aligned.m8n8.x4.shared.b16 {%0,%1,%2,%3}, [%4];" \
        : "=r"(r0), "=r"(r1), "=r"(r2), "=r"(r3) : "r"(addr))
#define LDU32(p) (*(const uint32_t*)(p))

// ---------------- x = emb + pos (fp32 + fp16 copy) -------------------------------
__global__ void k_add(const float4* __restrict__ a, const float4* __restrict__ b,
                      float4* __restrict__ o, uint2* __restrict__ o16) {
    int i = blockIdx.x * blockDim.x + threadIdx.x;
    float4 x = a[i], y = b[i];
    x.x += y.x; x.y += y.y; x.z += y.z; x.w += y.w;
    o[i] = x;
    uint2 h;
    h.x = h2pack(x.x, x.y);
    h.y = h2pack(x.z, x.w);
    o16[i] = h;
}

// ---------------- tiled transpose fp32 [R][C] -> fp16 [C][R], batched ------------
__global__ void k_tr(const float* __restrict__ in, __half* __restrict__ out,
                     int R, int C, long ibs, long obs,
                     const float* __restrict__ in1, const float* __restrict__ in2,
                     int zsplit) {
    __shared__ float t[32][33];
    int z = blockIdx.z;
    const float* base = in;
    if (zsplit > 0) {
        int wsel = z / zsplit;
        base = (wsel == 0) ? in : (wsel == 1) ? in1 : in2;
        z = z - wsel * zsplit;
    }
    const float* ip = base + (size_t)z * ibs;
    __half* op = out + (size_t)blockIdx.z * obs;
    int c0 = blockIdx.x * 32, r0 = blockIdx.y * 32;
    int tx = threadIdx.x, ty = threadIdx.y;
#pragma unroll
    for (int j = 0; j < 4; j++)
        t[ty + j*8][tx] = ip[(size_t)(r0 + ty + j*8) * C + c0 + tx];
    __syncthreads();
#pragma unroll
    for (int j = 0; j < 4; j++)
        op[(size_t)(c0 + ty + j*8) * R + r0 + tx] = __float2half_rn(t[tx][ty + j*8]);
}

// ---------------- fp16 mma GEMM, cp.async 3-stage, ldmatrix feeding --------------
#define PBY 80
#define STG_B (256 * PBY)
#define GEMM_SMEM (3 * STG_B)

__global__ __launch_bounds__(256, 2)
void k_gemm_h(const __half* __restrict__ Ag, const __half* __restrict__ BTg,
              float* __restrict__ Cg, __half* __restrict__ Cg16,
              int Nd, int Kd,
              const float* __restrict__ bias, const float* __restrict__ resid,
              int do_relu, int qkv_mode,
              __half* __restrict__ qd, float* __restrict__ kd,
              float* __restrict__ vd, __half* __restrict__ khd,
              __half* __restrict__ vtd) {
    extern __shared__ char smh[];
    uint32_t sb = smem_u32(smh);

    int tid = threadIdx.x;
    int lane = tid & 31, wid = tid >> 5;
    int wm = wid & 1, wn = wid >> 1;
    int gid = lane >> 2, qid = lane & 3;

    const __half* Ab = Ag + (size_t)blockIdx.y * 128 * Kd;
    const __half* Bb = BTg + (size_t)blockIdx.x * 128 * Kd;

    int cr = tid >> 2;
    int co = tid & 3;

    // ldmatrix per-thread offsets (within a stage)
    // A tile (mi): rows wm*64+mi*16+(lane&15), byte half (lane>>4)*16
    int a_row = lane & 15, a_half = (lane >> 4) * 16;
    uint32_t aoff[4];
#pragma unroll
    for (int mi = 0; mi < 4; mi++)
        aoff[mi] = (uint32_t)((wm * 64 + mi * 16 + a_row) * PBY + a_half);
    // B tiles (g2): rows wn*32 + g2*16 + (lane>>4)*8 + (lane&7), half ((lane>>3)&1)*16
    int b_row = (lane >> 4) * 8 + (lane & 7), b_half = ((lane >> 3) & 1) * 16;
    uint32_t boff[2];
#pragma unroll
    for (int g2 = 0; g2 < 2; g2++)
        boff[g2] = (uint32_t)(128 * PBY + (wn * 32 + g2 * 16 + b_row) * PBY + b_half);

    float acc[4][4][4];
#pragma unroll
    for (int i = 0; i < 4; i++)
#pragma unroll
        for (int j = 0; j < 4; j++)
#pragma unroll
            for (int r = 0; r < 4; r++) acc[i][j][r] = 0.f;

    int nk = Kd >> 5;

#define LOAD_STAGE(s, k0)                                                     \
    do {                                                                      \
        uint32_t A0 = sb + (s) * STG_B;                                       \
        uint32_t B0 = A0 + 128 * PBY;                                         \
        CP16(A0 + cr * PBY + co * 16,        Ab + (size_t)cr * Kd + (k0) + co * 8); \
        CP16(A0 + (cr + 64) * PBY + co * 16, Ab + (size_t)(cr + 64) * Kd + (k0) + co * 8); \
        CP16(B0 + cr * PBY + co * 16,        Bb + (size_t)cr * Kd + (k0) + co * 8); \
        CP16(B0 + (cr + 64) * PBY + co * 16, Bb + (size_t)(cr + 64) * Kd + (k0) + co * 8); \
        CP_COMMIT();                                                          \
    } while (0)

    LOAD_STAGE(0, 0);
    LOAD_STAGE(1, 32);

    int buf = 0;
    for (int kc = 0; kc < nk; kc++) {
        if (kc + 2 < nk) { CP_WAIT(1); } else { CP_WAIT(0); }
        __syncthreads();
        if (kc + 2 < nk) {
            int s = (kc + 2) % 3;
            LOAD_STAGE(s, (kc + 2) * 32);
        }
        uint32_t st = sb + buf * STG_B;
#pragma unroll
        for (int j = 0; j < 2; j++) {
            uint32_t jb = j * 32;
            unsigned af[4][4], bf[4][2];
#pragma unroll
            for (int mi = 0; mi < 4; mi++)
                LDSM4(af[mi][0], af[mi][1], af[mi][2], af[mi][3],
                      st + aoff[mi] + jb);
            LDSM4(bf[0][0], bf[0][1], bf[1][0], bf[1][1], st + boff[0] + jb);
            LDSM4(bf[2][0], bf[2][1], bf[3][0], bf[3][1], st + boff[1] + jb);
#pragma unroll
            for (int mi = 0; mi < 4; mi++)
#pragma unroll
                for (int ni = 0; ni < 4; ni++)
                    MMA_F16(acc[mi][ni], af[mi][0], af[mi][1], af[mi][2],
                            af[mi][3], bf[ni][0], bf[ni][1]);
        }
        buf = (buf + 1) % 3;
    }
#undef LOAD_STAGE

    // epilogue
    int bn = blockIdx.x * 128;
#pragma unroll
    for (int mi = 0; mi < 4; mi++) {
        int r0 = blockIdx.y * 128 + wm * 64 + mi * 16 + gid;
        int r1 = r0 + 8;
#pragma unroll
        for (int ni = 0; ni < 4; ni++) {
            int col = bn + wn * 32 + ni * 8 + 2 * qid;
            float2 v0 = make_float2(acc[mi][ni][0], acc[mi][ni][1]);
            float2 v1 = make_float2(acc[mi][ni][2], acc[mi][ni][3]);
            if (qkv_mode) {
                int which = col >> 10;
                int cc = col & 1023;
                int hh = cc >> 6, aa = cc & 63;
                int bb = r0 >> 11;
                int s0r = r0 & 2047, s1r = r1 & 2047;
                int hb_ = hh * B + bb;
                size_t d0 = (((size_t)hb_ * S + s0r) * A + aa);
                size_t d1 = (((size_t)hb_ * S + s1r) * A + aa);
                if (which == 0) {
                    *(uint32_t*)(qd + d0) = h2pack(v0.x, v0.y);
                    *(uint32_t*)(qd + d1) = h2pack(v1.x, v1.y);
                } else if (which == 1) {
                    *(float2*)(kd + d0) = v0;
                    *(float2*)(kd + d1) = v1;
                    *(uint32_t*)(khd + d0) = h2pack(v0.x, v0.y);
                    *(uint32_t*)(khd + d1) = h2pack(v1.x, v1.y);
                } else {
                    *(float2*)(vd + d0) = v0;
                    *(float2*)(vd + d1) = v1;
                    size_t vt0 = ((size_t)hb_ * A + aa) * S;
                    vtd[vt0 + s0r]     = __float2half_rn(v0.x);
                    vtd[vt0 + S + s0r] = __float2half_rn(v0.y);
                    vtd[vt0 + s1r]     = __float2half_rn(v1.x);
                    vtd[vt0 + S + s1r] = __float2half_rn(v1.y);
                }
            } else {
                if (bias) {
                    float2 bv = *(const float2*)(bias + col);
                    v0.x += bv.x; v0.y += bv.y; v1.x += bv.x; v1.y += bv.y;
                }
                if (resid) {
                    float2 q0 = *(const float2*)(resid + (size_t)r0 * Nd + col);
                    float2 q1 = *(const float2*)(resid + (size_t)r1 * Nd + col);
                    v0.x += q0.x; v0.y += q0.y; v1.x += q1.x; v1.y += q1.y;
                }
                if (do_relu) {
                    v0.x = fmaxf(v0.x, 0.f); v0.y = fmaxf(v0.y, 0.f);
                    v1.x = fmaxf(v1.x, 0.f); v1.y = fmaxf(v1.y, 0.f);
                }
                if (Cg) {
                    *(float2*)(Cg + (size_t)r0 * Nd + col) = v0;
                    *(float2*)(Cg + (size_t)r1 * Nd + col) = v1;
                }
                if (Cg16) {
                    *(uint32_t*)(Cg16 + (size_t)r0 * Nd + col) = h2pack(v0.x, v0.y);
                    *(uint32_t*)(Cg16 + (size_t)r1 * Nd + col) = h2pack(v1.x, v1.y);
                }
            }
        }
    }
}

// ---------------- fp16 tensor-core flash attention --------------------------------
#define APB 144
#define ATT_SMEM ((128 + 128 + 64 + 64) * APB)

__global__ __launch_bounds__(256, 2)
void k_attn(const __half* __restrict__ Qg, const __half* __restrict__ Khg,
            const __half* __restrict__ Vtg, __half* __restrict__ attn_out) {
    extern __shared__ char sma[];
    char* Qs = sma;
    char* Ps = Qs + 128 * APB;
    char* Ks = Ps + 128 * APB;
    char* Vt = Ks + 64 * APB;

    int tid = threadIdx.x, lane = tid & 31, wid = tid >> 5;
    int gid = lane >> 2, qid = lane & 3;
    int hb = blockIdx.y;
    int qt = gridDim.x - 1 - blockIdx.x;
    int h = hb / B, b = hb - h * B;
    int q0 = qt * 128;

    const uint4* Q4 = (const uint4*)(Qg + ((size_t)hb * S + q0) * A);
#pragma unroll
    for (int j = 0; j < 4; j++) {
        int i = tid + j * 256;
        int r = i >> 3, c = i & 7;
        *(uint4*)(Qs + r * APB + c * 16) = Q4[i];
    }

    int wr = wid * 16;
    int r0g = q0 + wr + gid, r1g = r0g + 8;
    float m0 = -INFINITY, m1 = -INFINITY, l0 = 0.f, l1 = 0.f;
    float o[8][4];
#pragma unroll
    for (int nt = 0; nt < 8; nt++)
#pragma unroll
        for (int c = 0; c < 4; c++) o[nt][c] = 0.f;

    const float scale = 0.03125f;
    int ntl = 2 * qt + 2;
    const uint4* K4 = (const uint4*)(Khg + (size_t)hb * S * A);
    const uint4* V4 = (const uint4*)(Vtg + (size_t)hb * A * S);

    for (int t = 0; t < ntl; t++) {
        int k0 = t * 64;
        __syncthreads();
#pragma unroll
        for (int j = 0; j < 2; j++) {
            int i = tid + j * 256;
            int r = i >> 3, c = i & 7;
            *(uint4*)(Ks + r * APB + c * 16) = K4[(size_t)(k0 + r) * 8 + c];
            *(uint4*)(Vt + r * APB + c * 16) = V4[(size_t)r * (S / 8) + (k0 >> 3) + c];
        }
        __syncthreads();

        if (k0 <= q0 + wr + 15) {
            float sa[8][4];
#pragma unroll
            for (int nt = 0; nt < 8; nt++)
#pragma unroll
                for (int c = 0; c < 4; c++) sa[nt][c] = 0.f;
#pragma unroll
            for (int j = 0; j < 4; j++) {
                int jb = j * 32;
                const char* pa0 = Qs + (wr + gid) * APB + qid * 4 + jb;
                const char* pa1 = Qs + (wr + gid + 8) * APB + qid * 4 + jb;
                unsigned a0 = LDU32(pa0), a1 = LDU32(pa1);
                unsigned a2 = LDU32(pa0 + 16), a3 = LDU32(pa1 + 16);
#pragma unroll
                for (int nt = 0; nt < 8; nt++) {
                    const char* pb = Ks + (nt * 8 + gid) * APB + qid * 4 + jb;
                    MMA_F16(sa[nt], a0, a1, a2, a3, LDU32(pb), LDU32(pb + 16));
                }
            }
            float mx0 = -INFINITY, mx1 = -INFINITY;
#pragma unroll
            for (int nt = 0; nt < 8; nt++) {
                int colb = k0 + nt * 8 + 2 * qid;
                sa[nt][0] = (colb     <= r0g) ? sa[nt][0] * scale : -INFINITY;
                sa[nt][1] = (colb + 1 <= r0g) ? sa[nt][1] * scale : -INFINITY;
                sa[nt][2] = (colb     <= r1g) ? sa[nt][2] * scale : -INFINITY;
                sa[nt][3] = (colb + 1 <= r1g) ? sa[nt][3] * scale : -INFINITY;
                mx0 = fmaxf(mx0, fmaxf(sa[nt][0], sa[nt][1]));
                mx1 = fmaxf(mx1, fmaxf(sa[nt][2], sa[nt][3]));
            }
            mx0 = fmaxf(mx0, __shfl_xor_sync(0xffffffff, mx0, 1));
            mx0 = fmaxf(mx0, __shfl_xor_sync(0xffffffff, mx0, 2));
            mx1 = fmaxf(mx1, __shfl_xor_sync(0xffffffff, mx1, 1));
            mx1 = fmaxf(mx1, __shfl_xor_sync(0xffffffff, mx1, 2));
            float mn0 = fmaxf(m0, mx0), mn1 = fmaxf(m1, mx1);
            float al0 = __expf(m0 - mn0), al1 = __expf(m1 - mn1);
            float sum0 = 0.f, sum1 = 0.f;
#pragma unroll
            for (int nt = 0; nt < 8; nt++) {
                sa[nt][0] = __expf(sa[nt][0] - mn0); sum0 += sa[nt][0];
                sa[nt][1] = __expf(sa[nt][1] - mn0); sum0 += sa[nt][1];
                sa[nt][2] = __expf(sa[nt][2] - mn1); sum1 += sa[nt][2];
                sa[nt][3] = __expf(sa[nt][3] - mn1); sum1 += sa[nt][3];
            }
            sum0 += __shfl_xor_sync(0xffffffff, sum0, 1);
            sum0 += __shfl_xor_sync(0xffffffff, sum0, 2);
            sum1 += __shfl_xor_sync(0xffffffff, sum1, 1);
            sum1 += __shfl_xor_sync(0xffffffff, sum1, 2);
            l0 = l0 * al0 + sum0;  m0 = mn0;
            l1 = l1 * al1 + sum1;  m1 = mn1;
#pragma unroll
            for (int nt = 0; nt < 8; nt++) {
                o[nt][0] *= al0; o[nt][1] *= al0;
                o[nt][2] *= al1; o[nt][3] *= al1;
            }
#pragma unroll
            for (int nt = 0; nt < 8; nt++) {
                *(uint32_t*)(Ps + (wr + gid) * APB + (nt * 8 + 2 * qid) * 2) =
                    h2pack(sa[nt][0], sa[nt][1]);
                *(uint32_t*)(Ps + (wr + gid + 8) * APB + (nt * 8 + 2 * qid) * 2) =
                    h2pack(sa[nt][2], sa[nt][3]);
            }
            __syncwarp();
#pragma unroll
            for (int j = 0; j < 4; j++) {
                int jb = j * 32;
                const char* pa0 = Ps + (wr + gid) * APB + qid * 4 + jb;
                const char* pa1 = Ps + (wr + gid + 8) * APB + qid * 4 + jb;
                unsigned a0 = LDU32(pa0), a1 = LDU32(pa1);
                unsigned a2 = LDU32(pa0 + 16), a3 = LDU32(pa1 + 16);
#pragma unroll
                for (int nt = 0; nt < 8; nt++) {
                    const char* pb = Vt + (nt * 8 + gid) * APB + qid * 4 + jb;
                    MMA_F16(o[nt], a0, a1, a2, a3, LDU32(pb), LDU32(pb + 16));
                }
            }
        }
    }

    float il0 = 1.f / l0, il1 = 1.f / l1;
    int row0 = b * S + q0 + wr + gid;
    int row1 = row0 + 8;
#pragma unroll
    for (int nt = 0; nt < 8; nt++) {
        int col = h * A + nt * 8 + 2 * qid;
        *(uint32_t*)(attn_out + (size_t)row0 * E + col) =
            h2pack(o[nt][0] * il0, o[nt][1] * il0);
        *(uint32_t*)(attn_out + (size_t)row1 * E + col) =
            h2pack(o[nt][2] * il1, o[nt][3] * il1);
    }
}

// ---------------- LayerNorm helpers ----------------------------------------------
__device__ __forceinline__ float4 ln_row(float4 x, int t, const float* gg,
                                         const float* bb, float* red) {
    float sum = x.x + x.y + x.z + x.w;
    float sq  = x.x*x.x + x.y*x.y + x.z*x.z + x.w*x.w;
#pragma unroll
    for (int off = 16; off; off >>= 1) {
        sum += __shfl_xor_sync(0xffffffff, sum, off);
        sq  += __shfl_xor_sync(0xffffffff, sq,  off);
    }
    if ((t & 31) == 0) { red[t >> 5] = sum; red[8 + (t >> 5)] = sq; }
    __syncthreads();
    float ts = 0.f, tq = 0.f;
#pragma unroll
    for (int i = 0; i < 8; i++) { ts += red[i]; tq += red[8 + i]; }
    float mu = ts * (1.f / E);
    float rstd = rsqrtf(tq * (1.f / E) - mu * mu + 1e-5f);
    float4 g4 = ((const float4*)gg)[t];
    float4 b4 = ((const float4*)bb)[t];
    float4 rr;
    rr.x = (x.x - mu) * rstd * g4.x + b4.x;
    rr.y = (x.y - mu) * rstd * g4.y + b4.y;
    rr.z = (x.z - mu) * rstd * g4.z + b4.z;
    rr.w = (x.w - mu) * rstd * g4.w + b4.w;
    return rr;
}

__global__ __launch_bounds__(256)
void k_ln(const float* __restrict__ a, const float* __restrict__ b,
          const float* __restrict__ gg, const float* __restrict__ bb,
          float* __restrict__ o, __half* __restrict__ o16) {
    __shared__ float red[16];
    int row = blockIdx.x;
    int t = threadIdx.x;
    float4 x = ((const float4*)(a + (size_t)row * E))[t];
    if (b) {
        float4 y = ((const float4*)(b + (size_t)row * E))[t];
        x.x += y.x; x.y += y.y; x.z += y.z; x.w += y.w;
    }
    float4 rr = ln_row(x, t, gg, bb, red);
    ((float4*)(o + (size_t)row * E))[t] = rr;
    if (o16) {
        uint2 hh;
        hh.x = h2pack(rr.x, rr.y);
        hh.y = h2pack(rr.z, rr.w);
        ((uint2*)(o16 + (size_t)row * E))[t] = hh;
    }
}

__global__ __launch_bounds__(256)
void k_ln2(const float* __restrict__ mha, const float* __restrict__ ff,
           const float* __restrict__ g1, const float* __restrict__ b1v,
           const float* __restrict__ g2, const float* __restrict__ b2v,
           float* __restrict__ out) {
    __shared__ float red[16];
    int row = blockIdx.x;
    int t = threadIdx.x;
    float4 xm = ((const float4*)(mha + (size_t)row * E))[t];
    float4 xf = ((const float4*)(ff + (size_t)row * E))[t];
    float4 x1;
    x1.x = xm.x + xf.x; x1.y = xm.y + xf.y;
    x1.z = xm.z + xf.z; x1.w = xm.w + xf.w;
    float4 r1 = ln_row(x1, t, g1, b1v, red);
    __syncthreads();
    float4 x2;
    x2.x = xm.x + r1.x; x2.y = xm.y + r1.y;
    x2.z = xm.z + r1.z; x2.w = xm.w + r1.w;
    float4 r2 = ln_row(x2, t, g2, b2v, red);
    ((float4*)(out + (size_t)row * E))[t] = r2;
}

// ---------------- launch ----------------------------------------------------------
extern "C" void kernel_launch(void* const* d_in, const int* in_sizes, int n_in,
                              void* d_out, int out_size) {
    const float* emb    = (const float*)d_in[0];
    const float* pos    = (const float*)d_in[1];
    const float* Wq     = (const float*)d_in[2];
    const float* Wk     = (const float*)d_in[3];
    const float* Wv     = (const float*)d_in[4];
    const float* Wproj  = (const float*)d_in[5];
    const float* W1     = (const float*)d_in[6];
    const float* b1     = (const float*)d_in[7];
    const float* W2     = (const float*)d_in[8];
    const float* b2     = (const float*)d_in[9];
    const float* gattn  = (const float*)d_in[10];
    const float* beattn = (const float*)d_in[11];
    const float* gffn   = (const float*)d_in[12];
    const float* beffn  = (const float*)d_in[13];
    const float* gout   = (const float*)d_in[14];
    const float* beout  = (const float*)d_in[15];

    float* out  = (float*)d_out;
    float* Kout = out + (size_t)M * E;
    float* Vout = out + (size_t)2 * M * E;

    float *px, *pqkv, *pmha, *pff;
    __half *px16, *pw, *pwp, *pw1, *pw2, *pq16, *pkh, *pvt, *pattn16, *pmha16, *phid16;
    cudaGetSymbolAddress((void**)&px,     g_x);
    cudaGetSymbolAddress((void**)&px16,   g_x16);
    cudaGetSymbolAddress((void**)&pw,     g_wqkvT);
    cudaGetSymbolAddress((void**)&pwp,    g_wpT);
    cudaGetSymbolAddress((void**)&pw1,    g_w1T);
    cudaGetSymbolAddress((void**)&pw2,    g_w2T);
    cudaGetSymbolAddress((void**)&pqkv,   g_qkv);
    cudaGetSymbolAddress((void**)&pq16,   g_q16);
    cudaGetSymbolAddress((void**)&pkh,    g_kh);
    cudaGetSymbolAddress((void**)&pvt,    g_vt);
    cudaGetSymbolAddress((void**)&pattn16,g_attn16);
    cudaGetSymbolAddress((void**)&pmha,   g_mha);
    cudaGetSymbolAddress((void**)&pmha16, g_mha16);
    cudaGetSymbolAddress((void**)&phid16, g_hid16);
    cudaGetSymbolAddress((void**)&pff,    g_ff);

    cudaFuncSetAttribute(k_attn, cudaFuncAttributeMaxDynamicSharedMemorySize,
                         ATT_SMEM);
    cudaFuncSetAttribute(k_gemm_h, cudaFuncAttributeMaxDynamicSharedMemorySize,
                         GEMM_SMEM);

    dim3 trb(32, 8);
    k_add<<<(M * E / 4) / 256, 256>>>((const float4*)emb, (const float4*)pos,
                                      (float4*)px, (uint2*)px16);
    k_tr<<<dim3(A/32, E/32, 3*H), trb>>>(Wq, pw, E, A, (long)E*A, (long)A*E,
                                         Wk, Wv, H);
    k_tr<<<dim3(E/32, E/32, 1), trb>>>(Wproj, pwp, E, E, 0, 0, nullptr, nullptr, 0);
    k_tr<<<dim3(FFD/32, E/32, 1), trb>>>(W1, pw1, E, FFD, 0, 0, nullptr, nullptr, 0);
    k_tr<<<dim3(E/32, FFD/32, 1), trb>>>(W2, pw2, FFD, E, 0, 0, nullptr, nullptr, 0);
    k_gemm_h<<<dim3(NQKV/128, M/128), 256, GEMM_SMEM>>>(
        px16, pw, nullptr, nullptr, NQKV, E, nullptr, nullptr, 0, 1,
        pq16, Kout, Vout, pkh, pvt);
    k_attn<<<dim3(S/128, H*B), 256, ATT_SMEM>>>(pq16, pkh, pvt, pattn16);
    k_gemm_h<<<dim3(E/128, M/128), 256, GEMM_SMEM>>>(
        pattn16, pwp, pqkv, nullptr, E, E, nullptr, px, 0, 0,
        nullptr, nullptr, nullptr, nullptr, nullptr);
    k_ln<<<M, 256>>>(pqkv, nullptr, gattn, beattn, pmha, pmha16);
    k_gemm_h<<<dim3(FFD/128, M/128), 256, GEMM_SMEM>>>(
        pmha16, pw1, nullptr, phid16, FFD, E, b1, nullptr, 0, 0,
        nullptr, nullptr, nullptr, nullptr, nullptr);
    k_gemm_h<<<dim3(E/128, M/128), 256, GEMM_SMEM>>>(
        phid16, pw2, pff, nullptr, E, FFD, b2, nullptr, 1, 0,
        nullptr, nullptr, nullptr, nullptr, nullptr);
    k_ln2<<<M, 256>>>(pmha, pff, gffn, beffn, gout, beout, out);
}

// round 16
// speedup vs baseline: 2.0101x; 1.0249x over previous
#include <cuda_runtime.h>
#include <cuda_fp16.h>
#include <math.h>
#include <stdint.h>

// Problem constants
#define E   1024
#define A   64
#define H   16
#define FFD 4096
#define B   2
#define S   2048
#define M   (B*S)
#define NQKV (3*E)

// ---------------- scratch (device globals) -----------------------------------
__device__ float  g_x[M*E];
__device__ __half g_x16[M*E];
__device__ __half g_wqkvT[NQKV*E];
__device__ __half g_wpT[E*E];
__device__ __half g_w1T[FFD*E];
__device__ __half g_w2T[E*FFD];
__device__ float  g_qkv[M*E];
__device__ __half g_q16[M*E];
__device__ __half g_kh[M*E];
__device__ __half g_vt[M*E];
__device__ __half g_attn16[M*E];
__device__ float  g_mha[M*E];
__device__ __half g_mha16[M*E];
__device__ __half g_hid16[M*FFD];
__device__ float  g_ff[M*E];

// ---------------- helpers -------------------------------------------------------
__device__ __forceinline__ uint32_t smem_u32(const void* p) {
    uint32_t r;
    asm("{ .reg .u64 t; cvta.to.shared.u64 t, %1; cvt.u32.u64 %0, t; }"
        : "=r"(r) : "l"(p));
    return r;
}
__device__ __forceinline__ uint32_t h2pack(float x, float y) {
    __half2 h = __floats2half2_rn(x, y);
    return *(uint32_t*)&h;
}
#define CP16(dst, src) \
    asm volatile("cp.async.cg.shared.global [%0], [%1], 16;" \
                 :: "r"(dst), "l"(src) : "memory")
#define CP_COMMIT() asm volatile("cp.async.commit_group;" ::: "memory")
#define CP_WAIT(n)  asm volatile("cp.async.wait_group %0;" :: "n"(n) : "memory")
#define MMA_F16(d, a0,a1,a2,a3, b0,b1)                                        \
    asm volatile(                                                             \
        "mma.sync.aligned.m16n8k16.row.col.f32.f16.f16.f32 "                  \
        "{%0,%1,%2,%3}, {%4,%5,%6,%7}, {%8,%9}, {%0,%1,%2,%3};"               \
        : "+f"((d)[0]), "+f"((d)[1]), "+f"((d)[2]), "+f"((d)[3])              \
        : "r"(a0), "r"(a1), "r"(a2), "r"(a3), "r"(b0), "r"(b1))
#define LDSM4(r0, r1, r2, r3, addr)                                           \
    asm volatile("ldmatrix.sync.aligned.m8n8.x4.shared.b16 {%0,%1,%2,%3}, [%4];" \
        : "=r"(r0), "=r"(r1), "=r"(r2), "=r"(r3) : "r"(addr))
#define LDU32(p) (*(const uint32_t*)(p))

// ---------------- x = emb + pos (fp32 + fp16 copy) -------------------------------
__global__ void k_add(const float4* __restrict__ a, const float4* __restrict__ b,
                      float4* __restrict__ o, uint2* __restrict__ o16) {
    int i = blockIdx.x * blockDim.x + threadIdx.x;
    float4 x = a[i], y = b[i];
    x.x += y.x; x.y += y.y; x.z += y.z; x.w += y.w;
    o[i] = x;
    uint2 h;
    h.x = h2pack(x.x, x.y);
    h.y = h2pack(x.z, x.w);
    o16[i] = h;
}

// ---------------- tiled transpose fp32 [R][C] -> fp16 [C][R], batched ------------
__global__ void k_tr(const float* __restrict__ in, __half* __restrict__ out,
                     int R, int C, long ibs, long obs,
                     const float* __restrict__ in1, const float* __restrict__ in2,
                     int zsplit) {
    __shared__ float t[32][33];
    int z = blockIdx.z;
    const float* base = in;
    if (zsplit > 0) {
        int wsel = z / zsplit;
        base = (wsel == 0) ? in : (wsel == 1) ? in1 : in2;
        z = z - wsel * zsplit;
    }
    const float* ip = base + (size_t)z * ibs;
    __half* op = out + (size_t)blockIdx.z * obs;
    int c0 = blockIdx.x * 32, r0 = blockIdx.y * 32;
    int tx = threadIdx.x, ty = threadIdx.y;
#pragma unroll
    for (int j = 0; j < 4; j++)
        t[ty + j*8][tx] = ip[(size_t)(r0 + ty + j*8) * C + c0 + tx];
    __syncthreads();
#pragma unroll
    for (int j = 0; j < 4; j++)
        op[(size_t)(c0 + ty + j*8) * R + r0 + tx] = __float2half_rn(t[tx][ty + j*8]);
}

// ---------------- fp16 mma GEMM, cp.async 3-stage, ldmatrix feeding --------------
#define PBY 80
#define STG_B (256 * PBY)
#define GEMM_SMEM (3 * STG_B)

__global__ __launch_bounds__(256, 2)
void k_gemm_h(const __half* __restrict__ Ag, const __half* __restrict__ BTg,
              float* __restrict__ Cg, __half* __restrict__ Cg16,
              int Nd, int Kd,
              const float* __restrict__ bias, const float* __restrict__ resid,
              int do_relu, int qkv_mode,
              __half* __restrict__ qd, float* __restrict__ kd,
              float* __restrict__ vd, __half* __restrict__ khd,
              __half* __restrict__ vtd) {
    extern __shared__ char smh[];
    uint32_t sb = smem_u32(smh);

    int tid = threadIdx.x;
    int lane = tid & 31, wid = tid >> 5;
    int wm = wid & 1, wn = wid >> 1;
    int gid = lane >> 2, qid = lane & 3;

    const __half* Ab = Ag + (size_t)blockIdx.y * 128 * Kd;
    const __half* Bb = BTg + (size_t)blockIdx.x * 128 * Kd;

    int cr = tid >> 2;
    int co = tid & 3;

    int a_row = lane & 15, a_half = (lane >> 4) * 16;
    uint32_t aoff[4];
#pragma unroll
    for (int mi = 0; mi < 4; mi++)
        aoff[mi] = (uint32_t)((wm * 64 + mi * 16 + a_row) * PBY + a_half);
    int b_row = (lane >> 4) * 8 + (lane & 7), b_half = ((lane >> 3) & 1) * 16;
    uint32_t boff[2];
#pragma unroll
    for (int g2 = 0; g2 < 2; g2++)
        boff[g2] = (uint32_t)(128 * PBY + (wn * 32 + g2 * 16 + b_row) * PBY + b_half);

    float acc[4][4][4];
#pragma unroll
    for (int i = 0; i < 4; i++)
#pragma unroll
        for (int j = 0; j < 4; j++)
#pragma unroll
            for (int r = 0; r < 4; r++) acc[i][j][r] = 0.f;

    int nk = Kd >> 5;

#define LOAD_STAGE(s, k0)                                                     \
    do {                                                                      \
        uint32_t A0 = sb + (s) * STG_B;                                       \
        uint32_t B0 = A0 + 128 * PBY;                                         \
        CP16(A0 + cr * PBY + co * 16,        Ab + (size_t)cr * Kd + (k0) + co * 8); \
        CP16(A0 + (cr + 64) * PBY + co * 16, Ab + (size_t)(cr + 64) * Kd + (k0) + co * 8); \
        CP16(B0 + cr * PBY + co * 16,        Bb + (size_t)cr * Kd + (k0) + co * 8); \
        CP16(B0 + (cr + 64) * PBY + co * 16, Bb + (size_t)(cr + 64) * Kd + (k0) + co * 8); \
        CP_COMMIT();                                                          \
    } while (0)

    LOAD_STAGE(0, 0);
    LOAD_STAGE(1, 32);

    int buf = 0;
    for (int kc = 0; kc < nk; kc++) {
        if (kc + 2 < nk) { CP_WAIT(1); } else { CP_WAIT(0); }
        __syncthreads();
        if (kc + 2 < nk) {
            int s = (kc + 2) % 3;
            LOAD_STAGE(s, (kc + 2) * 32);
        }
        uint32_t st = sb + buf * STG_B;
#pragma unroll
        for (int j = 0; j < 2; j++) {
            uint32_t jb = j * 32;
            unsigned af[4][4], bf[4][2];
#pragma unroll
            for (int mi = 0; mi < 4; mi++)
                LDSM4(af[mi][0], af[mi][1], af[mi][2], af[mi][3],
                      st + aoff[mi] + jb);
            LDSM4(bf[0][0], bf[0][1], bf[1][0], bf[1][1], st + boff[0] + jb);
            LDSM4(bf[2][0], bf[2][1], bf[3][0], bf[3][1], st + boff[1] + jb);
#pragma unroll
            for (int mi = 0; mi < 4; mi++)
#pragma unroll
                for (int ni = 0; ni < 4; ni++)
                    MMA_F16(acc[mi][ni], af[mi][0], af[mi][1], af[mi][2],
                            af[mi][3], bf[ni][0], bf[ni][1]);
        }
        buf = (buf + 1) % 3;
    }
#undef LOAD_STAGE

    // epilogue
    int bn = blockIdx.x * 128;
#pragma unroll
    for (int mi = 0; mi < 4; mi++) {
        int r0 = blockIdx.y * 128 + wm * 64 + mi * 16 + gid;
        int r1 = r0 + 8;
#pragma unroll
        for (int ni = 0; ni < 4; ni++) {
            int col = bn + wn * 32 + ni * 8 + 2 * qid;
            float2 v0 = make_float2(acc[mi][ni][0], acc[mi][ni][1]);
            float2 v1 = make_float2(acc[mi][ni][2], acc[mi][ni][3]);
            if (qkv_mode) {
                int which = col >> 10;
                int cc = col & 1023;
                int hh = cc >> 6, aa = cc & 63;
                int bb = r0 >> 11;
                int s0r = r0 & 2047, s1r = r1 & 2047;
                int hb_ = hh * B + bb;
                size_t d0 = (((size_t)hb_ * S + s0r) * A + aa);
                size_t d1 = (((size_t)hb_ * S + s1r) * A + aa);
                if (which == 0) {
                    *(uint32_t*)(qd + d0) = h2pack(v0.x, v0.y);
                    *(uint32_t*)(qd + d1) = h2pack(v1.x, v1.y);
                } else if (which == 1) {
                    *(float2*)(kd + d0) = v0;
                    *(float2*)(kd + d1) = v1;
                    *(uint32_t*)(khd + d0) = h2pack(v0.x, v0.y);
                    *(uint32_t*)(khd + d1) = h2pack(v1.x, v1.y);
                } else {
                    *(float2*)(vd + d0) = v0;
                    *(float2*)(vd + d1) = v1;
                    size_t vt0 = ((size_t)hb_ * A + aa) * S;
                    vtd[vt0 + s0r]     = __float2half_rn(v0.x);
                    vtd[vt0 + S + s0r] = __float2half_rn(v0.y);
                    vtd[vt0 + s1r]     = __float2half_rn(v1.x);
                    vtd[vt0 + S + s1r] = __float2half_rn(v1.y);
                }
            } else {
                if (bias) {
                    float2 bv = *(const float2*)(bias + col);
                    v0.x += bv.x; v0.y += bv.y; v1.x += bv.x; v1.y += bv.y;
                }
                if (resid) {
                    float2 q0 = *(const float2*)(resid + (size_t)r0 * Nd + col);
                    float2 q1 = *(const float2*)(resid + (size_t)r1 * Nd + col);
                    v0.x += q0.x; v0.y += q0.y; v1.x += q1.x; v1.y += q1.y;
                }
                if (do_relu) {
                    v0.x = fmaxf(v0.x, 0.f); v0.y = fmaxf(v0.y, 0.f);
                    v1.x = fmaxf(v1.x, 0.f); v1.y = fmaxf(v1.y, 0.f);
                }
                if (Cg) {
                    *(float2*)(Cg + (size_t)r0 * Nd + col) = v0;
                    *(float2*)(Cg + (size_t)r1 * Nd + col) = v1;
                }
                if (Cg16) {
                    *(uint32_t*)(Cg16 + (size_t)r0 * Nd + col) = h2pack(v0.x, v0.y);
                    *(uint32_t*)(Cg16 + (size_t)r1 * Nd + col) = h2pack(v1.x, v1.y);
                }
            }
        }
    }
}

// ---------------- fp16 tensor-core flash attention, ldmatrix feeding -------------
#define APB 144
#define ATT_SMEM ((128 + 128 + 64 + 64) * APB)

__global__ __launch_bounds__(256, 2)
void k_attn(const __half* __restrict__ Qg, const __half* __restrict__ Khg,
            const __half* __restrict__ Vtg, __half* __restrict__ attn_out) {
    extern __shared__ char sma[];
    uint32_t sbm = smem_u32(sma);
    char* Qs = sma;
    char* Ps = Qs + 128 * APB;
    char* Vt = Ps + 128 * APB + 64 * APB;   // Ks at +256*APB handled via offsets

    int tid = threadIdx.x, lane = tid & 31, wid = tid >> 5;
    int gid = lane >> 2, qid = lane & 3;
    int hb = blockIdx.y;
    int qt = gridDim.x - 1 - blockIdx.x;
    int h = hb / B, b = hb - h * B;
    int q0 = qt * 128;
    int wr = wid * 16;

    // ldmatrix address offsets
    int a_row = lane & 15, a_half = (lane >> 4) * 16;
    int b_row = (lane >> 4) * 8 + (lane & 7), b_half = ((lane >> 3) & 1) * 16;
    uint32_t qoffA = (uint32_t)((wr + a_row) * APB + a_half);             // Qs
    uint32_t poffA = (uint32_t)(128 * APB + (wr + a_row) * APB + a_half); // Ps
    uint32_t koffB[4], voffB[4];
#pragma unroll
    for (int g2 = 0; g2 < 4; g2++) {
        koffB[g2] = (uint32_t)(256 * APB + (g2 * 16 + b_row) * APB + b_half);
        voffB[g2] = (uint32_t)(320 * APB + (g2 * 16 + b_row) * APB + b_half);
    }

    // Q tile load
    const uint4* Q4 = (const uint4*)(Qg + ((size_t)hb * S + q0) * A);
#pragma unroll
    for (int j = 0; j < 4; j++) {
        int i = tid + j * 256;
        int r = i >> 3, c = i & 7;
        *(uint4*)(Qs + r * APB + c * 16) = Q4[i];
    }
    __syncthreads();

    // hoist Q fragments (tile-invariant)
    unsigned qf[4][4];
#pragma unroll
    for (int j = 0; j < 4; j++)
        LDSM4(qf[j][0], qf[j][1], qf[j][2], qf[j][3], sbm + qoffA + j * 32);

    int r0g = q0 + wr + gid, r1g = r0g + 8;
    float m0 = -INFINITY, m1 = -INFINITY, l0 = 0.f, l1 = 0.f;
    float o[8][4];
#pragma unroll
    for (int nt = 0; nt < 8; nt++)
#pragma unroll
        for (int c = 0; c < 4; c++) o[nt][c] = 0.f;

    const float scale = 0.03125f;
    int ntl = 2 * qt + 2;
    const uint4* K4 = (const uint4*)(Khg + (size_t)hb * S * A);
    const uint4* V4 = (const uint4*)(Vtg + (size_t)hb * A * S);
    char* Ks = sma + 256 * APB;

    for (int t = 0; t < ntl; t++) {
        int k0 = t * 64;
        __syncthreads();
#pragma unroll
        for (int j = 0; j < 2; j++) {
            int i = tid + j * 256;
            int r = i >> 3, c = i & 7;
            *(uint4*)(Ks + r * APB + c * 16) = K4[(size_t)(k0 + r) * 8 + c];
            *(uint4*)(Vt + r * APB + c * 16) = V4[(size_t)r * (S / 8) + (k0 >> 3) + c];
        }
        __syncthreads();

        if (k0 <= q0 + wr + 15) {
            // ---- QK^T ----
            float sa[8][4];
#pragma unroll
            for (int nt = 0; nt < 8; nt++)
#pragma unroll
                for (int c = 0; c < 4; c++) sa[nt][c] = 0.f;
#pragma unroll
            for (int j = 0; j < 4; j++) {
                uint32_t jb = j * 32;
                unsigned kf[8][2];
                LDSM4(kf[0][0], kf[0][1], kf[1][0], kf[1][1], sbm + koffB[0] + jb);
                LDSM4(kf[2][0], kf[2][1], kf[3][0], kf[3][1], sbm + koffB[1] + jb);
                LDSM4(kf[4][0], kf[4][1], kf[5][0], kf[5][1], sbm + koffB[2] + jb);
                LDSM4(kf[6][0], kf[6][1], kf[7][0], kf[7][1], sbm + koffB[3] + jb);
#pragma unroll
                for (int nt = 0; nt < 8; nt++)
                    MMA_F16(sa[nt], qf[j][0], qf[j][1], qf[j][2], qf[j][3],
                            kf[nt][0], kf[nt][1]);
            }
            // ---- scale + mask + online softmax ----
            float mx0 = -INFINITY, mx1 = -INFINITY;
#pragma unroll
            for (int nt = 0; nt < 8; nt++) {
                int colb = k0 + nt * 8 + 2 * qid;
                sa[nt][0] = (colb     <= r0g) ? sa[nt][0] * scale : -INFINITY;
                sa[nt][1] = (colb + 1 <= r0g) ? sa[nt][1] * scale : -INFINITY;
                sa[nt][2] = (colb     <= r1g) ? sa[nt][2] * scale : -INFINITY;
                sa[nt][3] = (colb + 1 <= r1g) ? sa[nt][3] * scale : -INFINITY;
                mx0 = fmaxf(mx0, fmaxf(sa[nt][0], sa[nt][1]));
                mx1 = fmaxf(mx1, fmaxf(sa[nt][2], sa[nt][3]));
            }
            mx0 = fmaxf(mx0, __shfl_xor_sync(0xffffffff, mx0, 1));
            mx0 = fmaxf(mx0, __shfl_xor_sync(0xffffffff, mx0, 2));
            mx1 = fmaxf(mx1, __shfl_xor_sync(0xffffffff, mx1, 1));
            mx1 = fmaxf(mx1, __shfl_xor_sync(0xffffffff, mx1, 2));
            float mn0 = fmaxf(m0, mx0), mn1 = fmaxf(m1, mx1);
            float al0 = __expf(m0 - mn0), al1 = __expf(m1 - mn1);
            float sum0 = 0.f, sum1 = 0.f;
#pragma unroll
            for (int nt = 0; nt < 8; nt++) {
                sa[nt][0] = __expf(sa[nt][0] - mn0); sum0 += sa[nt][0];
                sa[nt][1] = __expf(sa[nt][1] - mn0); sum0 += sa[nt][1];
                sa[nt][2] = __expf(sa[nt][2] - mn1); sum1 += sa[nt][2];
                sa[nt][3] = __expf(sa[nt][3] - mn1); sum1 += sa[nt][3];
            }
            sum0 += __shfl_xor_sync(0xffffffff, sum0, 1);
            sum0 += __shfl_xor_sync(0xffffffff, sum0, 2);
            sum1 += __shfl_xor_sync(0xffffffff, sum1, 1);
            sum1 += __shfl_xor_sync(0xffffffff, sum1, 2);
            l0 = l0 * al0 + sum0;  m0 = mn0;
            l1 = l1 * al1 + sum1;  m1 = mn1;
#pragma unroll
            for (int nt = 0; nt < 8; nt++) {
                o[nt][0] *= al0; o[nt][1] *= al0;
                o[nt][2] *= al1; o[nt][3] *= al1;
            }
            // ---- P -> smem (half, warp-private rows) ----
#pragma unroll
            for (int nt = 0; nt < 8; nt++) {
                *(uint32_t*)(Ps + (wr + gid) * APB + (nt * 8 + 2 * qid) * 2) =
                    h2pack(sa[nt][0], sa[nt][1]);
                *(uint32_t*)(Ps + (wr + gid + 8) * APB + (nt * 8 + 2 * qid) * 2) =
                    h2pack(sa[nt][2], sa[nt][3]);
            }
            __syncwarp();
            // ---- PV ----
#pragma unroll
            for (int j = 0; j < 4; j++) {
                uint32_t jb = j * 32;
                unsigned pf[4], vf[8][2];
                LDSM4(pf[0], pf[1], pf[2], pf[3], sbm + poffA + jb);
                LDSM4(vf[0][0], vf[0][1], vf[1][0], vf[1][1], sbm + voffB[0] + jb);
                LDSM4(vf[2][0], vf[2][1], vf[3][0], vf[3][1], sbm + voffB[1] + jb);
                LDSM4(vf[4][0], vf[4][1], vf[5][0], vf[5][1], sbm + voffB[2] + jb);
                LDSM4(vf[6][0], vf[6][1], vf[7][0], vf[7][1], sbm + voffB[3] + jb);
#pragma unroll
                for (int nt = 0; nt < 8; nt++)
                    MMA_F16(o[nt], pf[0], pf[1], pf[2], pf[3],
                            vf[nt][0], vf[nt][1]);
            }
        }
    }

    float il0 = 1.f / l0, il1 = 1.f / l1;
    int row0 = b * S + q0 + wr + gid;
    int row1 = row0 + 8;
#pragma unroll
    for (int nt = 0; nt < 8; nt++) {
        int col = h * A + nt * 8 + 2 * qid;
        *(uint32_t*)(attn_out + (size_t)row0 * E + col) =
            h2pack(o[nt][0] * il0, o[nt][1] * il0);
        *(uint32_t*)(attn_out + (size_t)row1 * E + col) =
            h2pack(o[nt][2] * il1, o[nt][3] * il1);
    }
}

// ---------------- LayerNorm helpers ----------------------------------------------
__device__ __forceinline__ float4 ln_row(float4 x, int t, const float* gg,
                                         const float* bb, float* red) {
    float sum = x.x + x.y + x.z + x.w;
    float sq  = x.x*x.x + x.y*x.y + x.z*x.z + x.w*x.w;
#pragma unroll
    for (int off = 16; off; off >>= 1) {
        sum += __shfl_xor_sync(0xffffffff, sum, off);
        sq  += __shfl_xor_sync(0xffffffff, sq,  off);
    }
    if ((t & 31) == 0) { red[t >> 5] = sum; red[8 + (t >> 5)] = sq; }
    __syncthreads();
    float ts = 0.f, tq = 0.f;
#pragma unroll
    for (int i = 0; i < 8; i++) { ts += red[i]; tq += red[8 + i]; }
    float mu = ts * (1.f / E);
    float rstd = rsqrtf(tq * (1.f / E) - mu * mu + 1e-5f);
    float4 g4 = ((const float4*)gg)[t];
    float4 b4 = ((const float4*)bb)[t];
    float4 rr;
    rr.x = (x.x - mu) * rstd * g4.x + b4.x;
    rr.y = (x.y - mu) * rstd * g4.y + b4.y;
    rr.z = (x.z - mu) * rstd * g4.z + b4.z;
    rr.w = (x.w - mu) * rstd * g4.w + b4.w;
    return rr;
}

__global__ __launch_bounds__(256)
void k_ln(const float* __restrict__ a, const float* __restrict__ b,
          const float* __restrict__ gg, const float* __restrict__ bb,
          float* __restrict__ o, __half* __restrict__ o16) {
    __shared__ float red[16];
    int row = blockIdx.x;
    int t = threadIdx.x;
    float4 x = ((const float4*)(a + (size_t)row * E))[t];
    if (b) {
        float4 y = ((const float4*)(b + (size_t)row * E))[t];
        x.x += y.x; x.y += y.y; x.z += y.z; x.w += y.w;
    }
    float4 rr = ln_row(x, t, gg, bb, red);
    ((float4*)(o + (size_t)row * E))[t] = rr;
    if (o16) {
        uint2 hh;
        hh.x = h2pack(rr.x, rr.y);
        hh.y = h2pack(rr.z, rr.w);
        ((uint2*)(o16 + (size_t)row * E))[t] = hh;
    }
}

__global__ __launch_bounds__(256)
void k_ln2(const float* __restrict__ mha, const float* __restrict__ ff,
           const float* __restrict__ g1, const float* __restrict__ b1v,
           const float* __restrict__ g2, const float* __restrict__ b2v,
           float* __restrict__ out) {
    __shared__ float red[16];
    int row = blockIdx.x;
    int t = threadIdx.x;
    float4 xm = ((const float4*)(mha + (size_t)row * E))[t];
    float4 xf = ((const float4*)(ff + (size_t)row * E))[t];
    float4 x1;
    x1.x = xm.x + xf.x; x1.y = xm.y + xf.y;
    x1.z = xm.z + xf.z; x1.w = xm.w + xf.w;
    float4 r1 = ln_row(x1, t, g1, b1v, red);
    __syncthreads();
    float4 x2;
    x2.x = xm.x + r1.x; x2.y = xm.y + r1.y;
    x2.z = xm.z + r1.z; x2.w = xm.w + r1.w;
    float4 r2 = ln_row(x2, t, g2, b2v, red);
    ((float4*)(out + (size_t)row * E))[t] = r2;
}

// ---------------- launch ----------------------------------------------------------
extern "C" void kernel_launch(void* const* d_in, const int* in_sizes, int n_in,
                              void* d_out, int out_size) {
    const float* emb    = (const float*)d_in[0];
    const float* pos    = (const float*)d_in[1];
    const float* Wq     = (const float*)d_in[2];
    const float* Wk     = (const float*)d_in[3];
    const float* Wv     = (const float*)d_in[4];
    const float* Wproj  = (const float*)d_in[5];
    const float* W1     = (const float*)d_in[6];
    const float* b1     = (const float*)d_in[7];
    const float* W2     = (const float*)d_in[8];
    const float* b2     = (const float*)d_in[9];
    const float* gattn  = (const float*)d_in[10];
    const float* beattn = (const float*)d_in[11];
    const float* gffn   = (const float*)d_in[12];
    const float* beffn  = (const float*)d_in[13];
    const float* gout   = (const float*)d_in[14];
    const float* beout  = (const float*)d_in[15];

    float* out  = (float*)d_out;
    float* Kout = out + (size_t)M * E;
    float* Vout = out + (size_t)2 * M * E;

    float *px, *pqkv, *pmha, *pff;
    __half *px16, *pw, *pwp, *pw1, *pw2, *pq16, *pkh, *pvt, *pattn16, *pmha16, *phid16;
    cudaGetSymbolAddress((void**)&px,     g_x);
    cudaGetSymbolAddress((void**)&px16,   g_x16);
    cudaGetSymbolAddress((void**)&pw,     g_wqkvT);
    cudaGetSymbolAddress((void**)&pwp,    g_wpT);
    cudaGetSymbolAddress((void**)&pw1,    g_w1T);
    cudaGetSymbolAddress((void**)&pw2,    g_w2T);
    cudaGetSymbolAddress((void**)&pqkv,   g_qkv);
    cudaGetSymbolAddress((void**)&pq16,   g_q16);
    cudaGetSymbolAddress((void**)&pkh,    g_kh);
    cudaGetSymbolAddress((void**)&pvt,    g_vt);
    cudaGetSymbolAddress((void**)&pattn16,g_attn16);
    cudaGetSymbolAddress((void**)&pmha,   g_mha);
    cudaGetSymbolAddress((void**)&pmha16, g_mha16);
    cudaGetSymbolAddress((void**)&phid16, g_hid16);
    cudaGetSymbolAddress((void**)&pff,    g_ff);

    cudaFuncSetAttribute(k_attn, cudaFuncAttributeMaxDynamicSharedMemorySize,
                         ATT_SMEM);
    cudaFuncSetAttribute(k_gemm_h, cudaFuncAttributeMaxDynamicSharedMemorySize,
                         GEMM_SMEM);

    dim3 trb(32, 8);
    k_add<<<(M * E / 4) / 256, 256>>>((const float4*)emb, (const float4*)pos,
                                      (float4*)px, (uint2*)px16);
    k_tr<<<dim3(A/32, E/32, 3*H), trb>>>(Wq, pw, E, A, (long)E*A, (long)A*E,
                                         Wk, Wv, H);
    k_tr<<<dim3(E/32, E/32, 1), trb>>>(Wproj, pwp, E, E, 0, 0, nullptr, nullptr, 0);
    k_tr<<<dim3(FFD/32, E/32, 1), trb>>>(W1, pw1, E, FFD, 0, 0, nullptr, nullptr, 0);
    k_tr<<<dim3(E/32, FFD/32, 1), trb>>>(W2, pw2, FFD, E, 0, 0, nullptr, nullptr, 0);
    k_gemm_h<<<dim3(NQKV/128, M/128), 256, GEMM_SMEM>>>(
        px16, pw, nullptr, nullptr, NQKV, E, nullptr, nullptr, 0, 1,
        pq16, Kout, Vout, pkh, pvt);
    k_attn<<<dim3(S/128, H*B), 256, ATT_SMEM>>>(pq16, pkh, pvt, pattn16);
    k_gemm_h<<<dim3(E/128, M/128), 256, GEMM_SMEM>>>(
        pattn16, pwp, pqkv, nullptr, E, E, nullptr, px, 0, 0,
        nullptr, nullptr, nullptr, nullptr, nullptr);
    k_ln<<<M, 256>>>(pqkv, nullptr, gattn, beattn, pmha, pmha16);
    k_gemm_h<<<dim3(FFD/128, M/128), 256, GEMM_SMEM>>>(
        pmha16, pw1, nullptr, phid16, FFD, E, b1, nullptr, 0, 0,
        nullptr, nullptr, nullptr, nullptr, nullptr);
    k_gemm_h<<<dim3(E/128, M/128), 256, GEMM_SMEM>>>(
        phid16, pw2, pff, nullptr, E, FFD, b2, nullptr, 1, 0,
        nullptr, nullptr, nullptr, nullptr, nullptr);
    k_ln2<<<M, 256>>>(pmha, pff, gffn, beffn, gout, beout, out);
}